// round 13
// baseline (speedup 1.0000x reference)
#include <cuda_runtime.h>
#include <cuda_bf16.h>
#include <math.h>
#include <stdint.h>

#define D_MODEL 768
#define NH      12
#define DH      64
#define SEQ     512
#define BATCH   8
#define ROWS    (BATCH*SEQ)   /* 4096 */
#define DFF     3072
#define NLAYERS 12
#define LN1E4   9.210340371976184f
#define WQKVO   (NLAYERS*D_MODEL*D_MODEL)
#define WFF     (NLAYERS*D_MODEL*DFF)
#define WQKV3   (NLAYERS*D_MODEL*3*D_MODEL)
#define WGH2    (NLAYERS*D_MODEL*2*DFF)

// ----------------------------------------------------------------------------
// Scratch (device globals; no allocation anywhere)
// ----------------------------------------------------------------------------
__device__ float g_x   [ROWS*D_MODEL];
__device__ float g_hn  [ROWS*D_MODEL];
__device__ float g_qkv [ROWS*3*D_MODEL];          // fused QKV output (fp32)
__device__ float2 g_rope[SEQ*32];                 // (cos, sin) per (pos, pair)

// bf16 hi/lo weight planes (converted once per call), B layout [K][N]
__device__ __nv_bfloat16 g_pwh[D_MODEL*D_MODEL], g_pwl[D_MODEL*D_MODEL];
__device__ __nv_bfloat16 g_bwh[D_MODEL*D_MODEL], g_bwl[D_MODEL*D_MODEL];
__device__ __nv_bfloat16 g_qkvWh[WQKV3], g_qkvWl[WQKV3];   // [L][768][2304] Q|K|V
__device__ __nv_bfloat16 g_woh[WQKVO], g_wol[WQKVO];
__device__ __nv_bfloat16 g_ghWh[WGH2], g_ghWl[WGH2];       // [L][768][6144] INTERLEAVED g/h
__device__ __nv_bfloat16 g_owh[WFF],   g_owl[WFF];
__device__ __nv_bfloat16 g_lwh[D_MODEL*1024], g_lwl[D_MODEL*1024];
// bf16 hi/lo activation planes
__device__ __nv_bfloat16 g_pah[ROWS*D_MODEL], g_pal[ROWS*D_MODEL];
__device__ __nv_bfloat16 g_bsh[ROWS*D_MODEL], g_bsl[ROWS*D_MODEL];
__device__ __nv_bfloat16 g_hnh[ROWS*D_MODEL], g_hnl[ROWS*D_MODEL];
__device__ __nv_bfloat16 g_oah[ROWS*D_MODEL], g_oal[ROWS*D_MODEL];
__device__ __nv_bfloat16 g_gsh[ROWS*DFF],     g_gsl[ROWS*DFF];

// ----------------------------------------------------------------------------
// helpers
// ----------------------------------------------------------------------------
__device__ __forceinline__ uint32_t smem_u32(const void* p) {
    return (uint32_t)__cvta_generic_to_shared(p);
}
__device__ __forceinline__ void splitf(float f, __nv_bfloat16& h, __nv_bfloat16& l) {
    h = __float2bfloat16_rn(f);
    l = __float2bfloat16_rn(f - __bfloat162float(h));
}
__device__ __forceinline__ void split2u(float f0, float f1, uint32_t& hi, uint32_t& lo) {
    __nv_bfloat16 h0, l0, h1, l1;
    splitf(f0, h0, l0); splitf(f1, h1, l1);
    __nv_bfloat162 hp(h0, h1), lp(l0, l1);
    hi = *(uint32_t*)&hp; lo = *(uint32_t*)&lp;
}
__device__ __forceinline__ void cp16(uint32_t dst, const void* src) {
    asm volatile("cp.async.cg.shared.global [%0], [%1], 16;" :: "r"(dst), "l"(src));
}
__device__ __forceinline__ void ldsm4(uint32_t r[4], uint32_t addr) {
    asm volatile("ldmatrix.sync.aligned.m8n8.x4.shared.b16 {%0,%1,%2,%3}, [%4];"
                 : "=r"(r[0]), "=r"(r[1]), "=r"(r[2]), "=r"(r[3]) : "r"(addr));
}
__device__ __forceinline__ void ldsm2(uint32_t r[2], uint32_t addr) {
    asm volatile("ldmatrix.sync.aligned.m8n8.x2.shared.b16 {%0,%1}, [%2];"
                 : "=r"(r[0]), "=r"(r[1]) : "r"(addr));
}
__device__ __forceinline__ void ldsm2t(uint32_t r[2], uint32_t addr) {
    asm volatile("ldmatrix.sync.aligned.m8n8.x2.trans.shared.b16 {%0,%1}, [%2];"
                 : "=r"(r[0]), "=r"(r[1]) : "r"(addr));
}
__device__ __forceinline__ void mma_bf16(float c[4], const uint32_t a[4], const uint32_t b[2]) {
    asm volatile(
        "mma.sync.aligned.m16n8k16.row.col.f32.bf16.bf16.f32 "
        "{%0,%1,%2,%3}, {%4,%5,%6,%7}, {%8,%9}, {%0,%1,%2,%3};"
        : "+f"(c[0]), "+f"(c[1]), "+f"(c[2]), "+f"(c[3])
        : "r"(a[0]), "r"(a[1]), "r"(a[2]), "r"(a[3]), "r"(b[0]), "r"(b[1]));
}

// ----------------------------------------------------------------------------
// conversion kernels
// ----------------------------------------------------------------------------
__global__ void cvt_split_kernel(const float* __restrict__ in,
                                 __nv_bfloat16* __restrict__ hi,
                                 __nv_bfloat16* __restrict__ lo, size_t n)
{
    size_t stride = (size_t)gridDim.x * blockDim.x * 4;
    for (size_t i = ((size_t)blockIdx.x * blockDim.x + threadIdx.x) * 4; i < n; i += stride) {
        float4 v = *(const float4*)(in + i);
        uint32_t h01, l01, h23, l23;
        split2u(v.x, v.y, h01, l01);
        split2u(v.z, v.w, h23, l23);
        *(uint32_t*)(hi+i)   = h01; *(uint32_t*)(hi+i+2) = h23;
        *(uint32_t*)(lo+i)   = l01; *(uint32_t*)(lo+i+2) = l23;
    }
}
// QKV concat: out [L][768][2304] from Wq/Wk/Wv [L][768][768]
__global__ void cvt_qkv_kernel(const float* __restrict__ Wq, const float* __restrict__ Wk,
                               const float* __restrict__ Wv,
                               __nv_bfloat16* __restrict__ hi, __nv_bfloat16* __restrict__ lo)
{
    size_t n4 = (size_t)WQKV3 / 4;
    size_t stride = (size_t)gridDim.x * blockDim.x;
    for (size_t i4 = (size_t)blockIdx.x * blockDim.x + threadIdx.x; i4 < n4; i4 += stride) {
        size_t i = i4 * 4;
        int col = (int)(i % 2304);
        size_t rl = i / 2304;
        int row = (int)(rl % D_MODEL);
        int layer = (int)(rl / D_MODEL);
        const float* src = (col < 768) ? Wq : ((col < 1536) ? Wk : Wv);
        size_t soff = (((size_t)layer * D_MODEL + row) * D_MODEL) + (col % 768);
        float4 v = *(const float4*)(src + soff);
        uint32_t h01, l01, h23, l23;
        split2u(v.x, v.y, h01, l01);
        split2u(v.z, v.w, h23, l23);
        *(uint32_t*)(hi+i)   = h01; *(uint32_t*)(hi+i+2) = h23;
        *(uint32_t*)(lo+i)   = l01; *(uint32_t*)(lo+i+2) = l23;
    }
}
// gate|hidden INTERLEAVED: out [L][768][6144], even col 2j = gate_j, odd col 2j+1 = hidden_j
__global__ void cvt_gh_kernel(const float* __restrict__ Wg, const float* __restrict__ Wh,
                              __nv_bfloat16* __restrict__ hi, __nv_bfloat16* __restrict__ lo)
{
    size_t n4 = (size_t)WGH2 / 4;   // each thread does 4 cols = 2 features
    size_t stride = (size_t)gridDim.x * blockDim.x;
    for (size_t i4 = (size_t)blockIdx.x * blockDim.x + threadIdx.x; i4 < n4; i4 += stride) {
        size_t i = i4 * 4;
        int col = (int)(i % 6144);          // multiple of 4
        size_t rl = i / 6144;
        int row = (int)(rl % D_MODEL);
        int layer = (int)(rl / D_MODEL);
        int j = col >> 1;                    // first feature index (even)
        size_t base = ((size_t)layer * D_MODEL + row) * DFF;
        float2 gv = *(const float2*)(Wg + base + j);
        float2 hv = *(const float2*)(Wh + base + j);
        uint32_t h01, l01, h23, l23;
        split2u(gv.x, hv.x, h01, l01);       // cols i, i+1 = gate_j, hidden_j
        split2u(gv.y, hv.y, h23, l23);       // cols i+2, i+3 = gate_{j+1}, hidden_{j+1}
        *(uint32_t*)(hi+i)   = h01; *(uint32_t*)(hi+i+2) = h23;
        *(uint32_t*)(lo+i)   = l01; *(uint32_t*)(lo+i+2) = l23;
    }
}
__global__ void cvt_label_kernel(const float* __restrict__ in,
                                 __nv_bfloat16* __restrict__ hi,
                                 __nv_bfloat16* __restrict__ lo)
{
    int idx = blockIdx.x * blockDim.x + threadIdx.x;
    if (idx >= D_MODEL * 1024) return;
    int row = idx >> 10, col = idx & 1023;
    float v = (col < 1000) ? in[row * 1000 + col] : 0.f;
    __nv_bfloat16 h, l; splitf(v, h, l);
    hi[idx] = h; lo[idx] = l;
}
__global__ void rope_table_kernel(float2* __restrict__ t)
{
    int idx = blockIdx.x * blockDim.x + threadIdx.x;
    if (idx >= SEQ * 32) return;
    int j = idx & 31, l = idx >> 5;
    float theta = expf(-(float)j * (LN1E4 / 32.f));
    float s, c; sincosf((float)l * theta, &s, &c);
    t[idx] = make_float2(c, s);
}

// ----------------------------------------------------------------------------
// bf16x3 split GEMM (R12 core, BK=32 via two sub-stages per pipeline stage).
// C = (Ah+Al)@(Bh+Bl) - Al*Bl, fp32 accum. K % 32 == 0.
// SILU=true: interleaved (gate,hidden) columns; writes silu(g)*h bf16 planes.
// Dynamic smem: 2 stages * 2 sub-stages * 20992B = 83968B.
// ----------------------------------------------------------------------------
template<bool ACC, bool BIAS, bool SILU>
__global__ __launch_bounds__(256, 2)
void bf16_gemm_kernel(const __nv_bfloat16* __restrict__ Ah, const __nv_bfloat16* __restrict__ Al,
                      const __nv_bfloat16* __restrict__ Bh, const __nv_bfloat16* __restrict__ Bl,
                      const float* __restrict__ bias, float* __restrict__ C,
                      __nv_bfloat16* __restrict__ Oh, __nv_bfloat16* __restrict__ Ol,
                      int M, int N, int NB, int K)
{
    constexpr int A_HI = 0, A_LO = 6144, B_HI = 12288, B_LO = 16640;
    constexpr int SUB = 20992, STG = 2 * SUB;      // BK=32 stage = 2 BK=16 sub-stages
    extern __shared__ __align__(128) uint8_t smem[];   // 2 * STG = 83968

    const int tid  = threadIdx.x;
    const int lane = tid & 31;
    const int warp = tid >> 5;
    const int wm   = warp >> 2;
    const int wn   = warp & 3;
    const int grp  = lane >> 2;
    const int tg   = lane & 3;
    const int m0 = blockIdx.y * 128;
    const int n0 = blockIdx.x * 128;

    const int ar = tid >> 1;
    const int kr = tid >> 4;
    const __nv_bfloat16* pAh = Ah + (size_t)(m0 + ar) * K + (tid & 1) * 8;
    const __nv_bfloat16* pAl = Al + (size_t)(m0 + ar) * K + (tid & 1) * 8;
    const __nv_bfloat16* pBh = Bh + (size_t)kr * NB + n0 + (tid & 15) * 8;
    const __nv_bfloat16* pBl = Bl + (size_t)kr * NB + n0 + (tid & 15) * 8;
    const uint32_t sb   = smem_u32(smem);
    const uint32_t adst = ar * 48 + (tid & 1) * 16;
    const uint32_t bdst = kr * 272 + (tid & 15) * 16;

    const int l16 = lane & 15;
    uint32_t aoff[4], boff[4];
    #pragma unroll
    for (int mt = 0; mt < 4; mt++)
        aoff[mt] = (uint32_t)((wm*64 + mt*16 + l16) * 48 + ((lane >> 4) & 1) * 16);
    #pragma unroll
    for (int nt = 0; nt < 4; nt++)
        boff[nt] = (uint32_t)(l16 * 272 + (wn*32 + nt*8) * 2);

    float acc[4][4][4];
    #pragma unroll
    for (int i = 0; i < 4; i++)
        #pragma unroll
        for (int j = 0; j < 4; j++)
            #pragma unroll
            for (int c = 0; c < 4; c++) acc[i][j][c] = 0.f;

    const int nk = K >> 5;    // BK=32 iterations
    // prologue: stage k-tile 0 (both sub-tiles) into stage 0
    #pragma unroll
    for (int sub = 0; sub < 2; sub++) {
        const uint32_t s = sb + sub * SUB;
        const size_t ka = (size_t)sub * 16;
        cp16(s + A_HI + adst, pAh + ka);
        cp16(s + A_LO + adst, pAl + ka);
        cp16(s + B_HI + bdst, pBh + ka * NB);
        cp16(s + B_LO + bdst, pBl + ka * NB);
    }
    asm volatile("cp.async.commit_group;" ::: "memory");

    for (int kt = 0; kt < nk; kt++) {
        const int buf = kt & 1;
        if (kt + 1 < nk) {
            const uint32_t sB = sb + (buf ^ 1) * STG;
            const size_t kb = (size_t)(kt + 1) * 32;
            #pragma unroll
            for (int sub = 0; sub < 2; sub++) {
                const uint32_t s = sB + sub * SUB;
                const size_t ka = kb + sub * 16;
                cp16(s + A_HI + adst, pAh + ka);
                cp16(s + A_LO + adst, pAl + ka);
                cp16(s + B_HI + bdst, pBh + ka * NB);
                cp16(s + B_LO + bdst, pBl + ka * NB);
            }
            asm volatile("cp.async.commit_group;" ::: "memory");
            asm volatile("cp.async.wait_group 1;" ::: "memory");
        } else {
            asm volatile("cp.async.wait_group 0;" ::: "memory");
        }
        __syncthreads();

        #pragma unroll
        for (int sub = 0; sub < 2; sub++) {
            const uint32_t s = sb + buf * STG + sub * SUB;
            uint32_t bh[4][2], bl[4][2];
            #pragma unroll
            for (int nt = 0; nt < 4; nt++) {
                ldsm2t(bh[nt], s + B_HI + boff[nt]);
                ldsm2t(bl[nt], s + B_LO + boff[nt]);
            }
            #pragma unroll
            for (int mt = 0; mt < 4; mt++) {
                uint32_t ah[4], al[4];
                ldsm4(ah, s + A_HI + aoff[mt]);
                ldsm4(al, s + A_LO + aoff[mt]);
                #pragma unroll
                for (int nt = 0; nt < 4; nt++) {
                    mma_bf16(acc[mt][nt], ah, bh[nt]);
                    mma_bf16(acc[mt][nt], al, bh[nt]);
                    mma_bf16(acc[mt][nt], ah, bl[nt]);
                }
            }
        }
        __syncthreads();
    }

    if (SILU) {
        #pragma unroll
        for (int mt = 0; mt < 4; mt++) {
            #pragma unroll
            for (int nt = 0; nt < 4; nt++) {
                int col  = n0 + wn*32 + nt*8 + tg*2;    // even
                int feat = col >> 1;
                int row0 = m0 + wm*64 + mt*16 + grp;
                {
                    float g = acc[mt][nt][0], hv = acc[mt][nt][1];
                    float r = (g / (1.f + expf(-g))) * hv;
                    __nv_bfloat16 hh, ll; splitf(r, hh, ll);
                    size_t off = (size_t)row0 * DFF + feat;
                    Oh[off] = hh; Ol[off] = ll;
                }
                {
                    float g = acc[mt][nt][2], hv = acc[mt][nt][3];
                    float r = (g / (1.f + expf(-g))) * hv;
                    __nv_bfloat16 hh, ll; splitf(r, hh, ll);
                    size_t off = (size_t)(row0 + 8) * DFF + feat;
                    Oh[off] = hh; Ol[off] = ll;
                }
            }
        }
    } else {
        #pragma unroll
        for (int mt = 0; mt < 4; mt++) {
            #pragma unroll
            for (int nt = 0; nt < 4; nt++) {
                #pragma unroll
                for (int c = 0; c < 4; c++) {
                    int row = m0 + wm*64 + mt*16 + grp + ((c >= 2) ? 8 : 0);
                    int col = n0 + wn*32 + nt*8 + tg*2 + (c & 1);
                    if (col < N) {
                        float v = acc[mt][nt][c];
                        if (BIAS) v += bias[col];
                        size_t off = (size_t)row * N + col;
                        if (ACC) v += C[off];
                        C[off] = v;
                    }
                }
            }
        }
    }
}

// ----------------------------------------------------------------------------
// Fused flash attention (validated R10)
// ----------------------------------------------------------------------------
__global__ __launch_bounds__(128)
void flash_kernel(const float* __restrict__ qkv, const float2* __restrict__ rope,
                  __nv_bfloat16* __restrict__ Oh, __nv_bfloat16* __restrict__ Ol)
{
    __shared__ __nv_bfloat16 KS[2][64][72];
    __shared__ __nv_bfloat16 VS[2][64][72];

    const int mb = blockIdx.x;
    const int bh = blockIdx.y;
    const int b = bh / NH, h = bh % NH;
    const int tid = threadIdx.x, lane = tid & 31, w = tid >> 5;
    const int grp = lane >> 2, tg = lane & 3;
    const int l16 = lane & 15;

    const int srow = tid >> 1;
    const int sch  = (tid & 1) * 32;

    {
        int pos = mb*64 + srow;
        size_t base = ((size_t)(b*SEQ + pos)) * 2304 + h*DH + sch;
        #pragma unroll
        for (int p = 0; p < 16; p++) {
            int c = sch + 2*p;
            float2 qv = *(const float2*)(qkv + base + 2*p);
            float2 cs = rope[pos*32 + (c >> 1)];
            float xr = qv.x*cs.x - qv.y*cs.y;
            float xi = qv.x*cs.y + qv.y*cs.x;
            uint32_t hp, lp; split2u(xr, xi, hp, lp);
            *(uint32_t*)&KS[0][srow][c] = hp;
            *(uint32_t*)&KS[1][srow][c] = lp;
        }
    }
    __syncthreads();
    uint32_t Qa[4][2][4];
    #pragma unroll
    for (int k0 = 0; k0 < 4; k0++) {
        ldsm4(Qa[k0][0], smem_u32(&KS[0][w*16 + l16][k0*16 + ((lane >> 4) & 1)*8]));
        ldsm4(Qa[k0][1], smem_u32(&KS[1][w*16 + l16][k0*16 + ((lane >> 4) & 1)*8]));
    }
    __syncthreads();

    float O[8][4];
    #pragma unroll
    for (int dt = 0; dt < 8; dt++)
        #pragma unroll
        for (int c = 0; c < 4; c++) O[dt][c] = 0.f;
    float mrow[2] = {-1e30f, -1e30f};
    float lrow[2] = {0.f, 0.f};

    const int myrow0 = mb*64 + w*16 + grp;
    const int myrow1 = myrow0 + 8;

    for (int nb = 0; nb <= mb; nb++) {
        {
            int pos = nb*64 + srow;
            size_t kbase = ((size_t)(b*SEQ + pos)) * 2304 + 768 + h*DH + sch;
            #pragma unroll
            for (int p = 0; p < 16; p++) {
                int c = sch + 2*p;
                float2 kv = *(const float2*)(qkv + kbase + 2*p);
                float2 cs = rope[pos*32 + (c >> 1)];
                float xr = kv.x*cs.x - kv.y*cs.y;
                float xi = kv.x*cs.y + kv.y*cs.x;
                uint32_t hp, lp; split2u(xr, xi, hp, lp);
                *(uint32_t*)&KS[0][srow][c] = hp;
                *(uint32_t*)&KS[1][srow][c] = lp;
            }
            size_t vbase = kbase + 768;
            #pragma unroll
            for (int p = 0; p < 8; p++) {
                float4 vv = *(const float4*)(qkv + vbase + 4*p);
                int c = sch + 4*p;
                uint32_t h01, l01, h23, l23;
                split2u(vv.x, vv.y, h01, l01);
                split2u(vv.z, vv.w, h23, l23);
                *(uint32_t*)&VS[0][srow][c]   = h01;
                *(uint32_t*)&VS[0][srow][c+2] = h23;
                *(uint32_t*)&VS[1][srow][c]   = l01;
                *(uint32_t*)&VS[1][srow][c+2] = l23;
            }
        }
        __syncthreads();

        float S[8][4];
        #pragma unroll
        for (int nt = 0; nt < 8; nt++)
            #pragma unroll
            for (int c = 0; c < 4; c++) S[nt][c] = 0.f;
        #pragma unroll
        for (int k0 = 0; k0 < 4; k0++) {
            #pragma unroll
            for (int nt = 0; nt < 8; nt++) {
                uint32_t kh2[2], kl2[2];
                uint32_t kaddr_h = smem_u32(&KS[0][nt*8 + (l16 & 7)][k0*16 + ((l16 >> 3) & 1)*8]);
                uint32_t kaddr_l = smem_u32(&KS[1][nt*8 + (l16 & 7)][k0*16 + ((l16 >> 3) & 1)*8]);
                ldsm2(kh2, kaddr_h);
                ldsm2(kl2, kaddr_l);
                mma_bf16(S[nt], Qa[k0][0], kh2);
                mma_bf16(S[nt], Qa[k0][1], kh2);
                mma_bf16(S[nt], Qa[k0][0], kl2);
            }
        }
        #pragma unroll
        for (int nt = 0; nt < 8; nt++) {
            #pragma unroll
            for (int c = 0; c < 4; c++) {
                float v = S[nt][c] * 0.125f;
                if (nb == mb) {
                    int col = nb*64 + nt*8 + tg*2 + (c & 1);
                    int row = (c >= 2) ? myrow1 : myrow0;
                    if (col > row) v = -1e30f;
                }
                S[nt][c] = v;
            }
        }

        float mx0 = -1e30f, mx1 = -1e30f;
        #pragma unroll
        for (int nt = 0; nt < 8; nt++) {
            mx0 = fmaxf(mx0, fmaxf(S[nt][0], S[nt][1]));
            mx1 = fmaxf(mx1, fmaxf(S[nt][2], S[nt][3]));
        }
        mx0 = fmaxf(mx0, __shfl_xor_sync(0xffffffffu, mx0, 1));
        mx0 = fmaxf(mx0, __shfl_xor_sync(0xffffffffu, mx0, 2));
        mx1 = fmaxf(mx1, __shfl_xor_sync(0xffffffffu, mx1, 1));
        mx1 = fmaxf(mx1, __shfl_xor_sync(0xffffffffu, mx1, 2));
        float mn0 = fmaxf(mrow[0], mx0), mn1 = fmaxf(mrow[1], mx1);
        float sc0 = __expf(mrow[0] - mn0), sc1 = __expf(mrow[1] - mn1);
        float sum0 = 0.f, sum1 = 0.f;
        #pragma unroll
        for (int nt = 0; nt < 8; nt++) {
            S[nt][0] = __expf(S[nt][0] - mn0);
            S[nt][1] = __expf(S[nt][1] - mn0);
            S[nt][2] = __expf(S[nt][2] - mn1);
            S[nt][3] = __expf(S[nt][3] - mn1);
            sum0 += S[nt][0] + S[nt][1];
            sum1 += S[nt][2] + S[nt][3];
        }
        sum0 += __shfl_xor_sync(0xffffffffu, sum0, 1);
        sum0 += __shfl_xor_sync(0xffffffffu, sum0, 2);
        sum1 += __shfl_xor_sync(0xffffffffu, sum1, 1);
        sum1 += __shfl_xor_sync(0xffffffffu, sum1, 2);
        lrow[0] = lrow[0]*sc0 + sum0;
        lrow[1] = lrow[1]*sc1 + sum1;
        mrow[0] = mn0; mrow[1] = mn1;
        #pragma unroll
        for (int dt = 0; dt < 8; dt++) {
            O[dt][0] *= sc0; O[dt][1] *= sc0;
            O[dt][2] *= sc1; O[dt][3] *= sc1;
        }

        #pragma unroll
        for (int k0p = 0; k0p < 4; k0p++) {
            const int n0t = 2*k0p, n1t = 2*k0p + 1;
            uint32_t pah[4], pal[4];
            split2u(S[n0t][0], S[n0t][1], pah[0], pal[0]);
            split2u(S[n0t][2], S[n0t][3], pah[1], pal[1]);
            split2u(S[n1t][0], S[n1t][1], pah[2], pal[2]);
            split2u(S[n1t][2], S[n1t][3], pah[3], pal[3]);
            #pragma unroll
            for (int dt = 0; dt < 8; dt++) {
                uint32_t vh2[2], vl2[2];
                ldsm2t(vh2, smem_u32(&VS[0][k0p*16 + l16][dt*8]));
                ldsm2t(vl2, smem_u32(&VS[1][k0p*16 + l16][dt*8]));
                mma_bf16(O[dt], pah, vh2);
                mma_bf16(O[dt], pal, vh2);
                mma_bf16(O[dt], pah, vl2);
            }
        }
        __syncthreads();
    }

    float inv0 = 1.f / lrow[0], inv1 = 1.f / lrow[1];
    #pragma unroll
    for (int dt = 0; dt < 8; dt++) {
        #pragma unroll
        for (int c = 0; c < 4; c++) {
            int row = (c >= 2) ? myrow1 : myrow0;
            int col = h*DH + dt*8 + tg*2 + (c & 1);
            float v = O[dt][c] * ((c >= 2) ? inv1 : inv0);
            __nv_bfloat16 hh, ll; splitf(v, hh, ll);
            size_t off = ((size_t)(b*SEQ + row)) * D_MODEL + col;
            Oh[off] = hh; Ol[off] = ll;
        }
    }
}

// ----------------------------------------------------------------------------
// Legacy SIMT SGEMM (tiny-N heads: N=2, N=4)
// ----------------------------------------------------------------------------
template<bool ACC, bool BIAS>
__global__ void gemm_kernel(const float* __restrict__ A, const float* __restrict__ B,
                            const float* __restrict__ bias, float* __restrict__ C,
                            int M, int N, int K)
{
    __shared__ float As[16][65];
    __shared__ float Bs[16][64];
    const int tid = threadIdx.x;
    const int tx = tid & 15, ty = tid >> 4;
    const int m0 = blockIdx.y * 64, n0 = blockIdx.x * 64;
    const int arow = tid >> 2, akk = (tid & 3) * 4;
    const int bkk = ty, bcol = tx * 4;

    float acc[4][4];
    #pragma unroll
    for (int i = 0; i < 4; i++)
        #pragma unroll
        for (int j = 0; j < 4; j++) acc[i][j] = 0.f;

    for (int k0 = 0; k0 < K; k0 += 16) {
        float4 av = *(const float4*)(A + (size_t)(m0 + arow) * K + k0 + akk);
        As[akk+0][arow] = av.x; As[akk+1][arow] = av.y;
        As[akk+2][arow] = av.z; As[akk+3][arow] = av.w;
        {
            int gn = n0 + bcol;
            const float* Bp = B + (size_t)(k0 + bkk) * N + gn;
            float4 bv;
            if (gn + 3 < N) bv = *(const float4*)Bp;
            else {
                bv.x = (gn+0 < N) ? Bp[0] : 0.f;
                bv.y = (gn+1 < N) ? Bp[1] : 0.f;
                bv.z = (gn+2 < N) ? Bp[2] : 0.f;
                bv.w = (gn+3 < N) ? Bp[3] : 0.f;
            }
            *(float4*)&Bs[bkk][bcol] = bv;
        }
        __syncthreads();
        #pragma unroll
        for (int kk = 0; kk < 16; kk++) {
            float a0 = As[kk][ty*4+0], a1 = As[kk][ty*4+1];
            float a2 = As[kk][ty*4+2], a3 = As[kk][ty*4+3];
            float4 bv = *(const float4*)&Bs[kk][tx*4];
            acc[0][0] += a0*bv.x; acc[0][1] += a0*bv.y; acc[0][2] += a0*bv.z; acc[0][3] += a0*bv.w;
            acc[1][0] += a1*bv.x; acc[1][1] += a1*bv.y; acc[1][2] += a1*bv.z; acc[1][3] += a1*bv.w;
            acc[2][0] += a2*bv.x; acc[2][1] += a2*bv.y; acc[2][2] += a2*bv.z; acc[2][3] += a2*bv.w;
            acc[3][0] += a3*bv.x; acc[3][1] += a3*bv.y; acc[3][2] += a3*bv.z; acc[3][3] += a3*bv.w;
        }
        __syncthreads();
    }
    #pragma unroll
    for (int i = 0; i < 4; i++) {
        int gm = m0 + ty*4 + i;
        #pragma unroll
        for (int j = 0; j < 4; j++) {
            int gn = n0 + tx*4 + j;
            if (gn < N) {
                float v = acc[i][j];
                if (BIAS) v += bias[gn];
                size_t off = (size_t)gm * N + gn;
                if (ACC) v += C[off];
                C[off] = v;
            }
        }
    }
}

// ----------------------------------------------------------------------------
// box Fourier features -> bf16 hi/lo planes
// ----------------------------------------------------------------------------
__global__ void boxsin_kernel(const float* __restrict__ box,
                              __nv_bfloat16* __restrict__ h, __nv_bfloat16* __restrict__ l)
{
    int idx = blockIdx.x * blockDim.x + threadIdx.x;     // ROWS*4*96
    if (idx >= ROWS*4*96) return;
    int j   = idx % 96;
    int i   = (idx / 96) & 3;
    int row = idx / 384;
    float theta = expf(-(float)j * (LN1E4 / 96.f));
    float ang = box[row*4 + i] * theta;
    float s, c;
    sincosf(ang, &s, &c);
    size_t off = (size_t)row*D_MODEL + i*192 + 2*j;
    __nv_bfloat16 hh, ll;
    splitf(c, hh, ll); h[off] = hh;   l[off] = ll;
    splitf(s, hh, ll); h[off+1] = hh; l[off+1] = ll;
}

// ----------------------------------------------------------------------------
// RMSNorm -> optional f32 out + optional bf16 hi/lo planes
// ----------------------------------------------------------------------------
__global__ void rmsnorm_kernel(const float* __restrict__ x, const float* __restrict__ w,
                               float* __restrict__ out,
                               __nv_bfloat16* __restrict__ oh, __nv_bfloat16* __restrict__ ol)
{
    __shared__ float red[256];
    int row = blockIdx.x;
    const float* xr = x + (size_t)row * D_MODEL;
    float s = 0.f;
    for (int i = threadIdx.x; i < D_MODEL; i += 256) { float v = xr[i]; s += v*v; }
    red[threadIdx.x] = s; __syncthreads();
    for (int off = 128; off > 0; off >>= 1) {
        if (threadIdx.x < off) red[threadIdx.x] += red[threadIdx.x + off];
        __syncthreads();
    }
    float inv = rsqrtf(red[0] / (float)D_MODEL + 1e-6f);
    for (int i = threadIdx.x; i < D_MODEL; i += 256) {
        float v = xr[i] * inv * w[i];
        if (out) out[(size_t)row * D_MODEL + i] = v;
        if (oh) {
            __nv_bfloat16 hh, ll; splitf(v, hh, ll);
            oh[(size_t)row * D_MODEL + i] = hh;
            ol[(size_t)row * D_MODEL + i] = ll;
        }
    }
}

// ----------------------------------------------------------------------------
// Launch
// ----------------------------------------------------------------------------
extern "C" void kernel_launch(void* const* d_in, const int* in_sizes, int n_in,
                              void* d_out, int out_size)
{
    const float* patch        = (const float*)d_in[0];
    const float* box          = (const float*)d_in[1];
    const float* patch_W      = (const float*)d_in[2];
    const float* patch_b      = (const float*)d_in[3];
    const float* box_W        = (const float*)d_in[4];
    const float* box_b        = (const float*)d_in[5];
    const float* Wq           = (const float*)d_in[6];
    const float* Wk           = (const float*)d_in[7];
    const float* Wv           = (const float*)d_in[8];
    const float* Wo           = (const float*)d_in[9];
    const float* attn_norm_w  = (const float*)d_in[10];
    const float* gate_W       = (const float*)d_in[11];
    const float* hidden_W     = (const float*)d_in[12];
    const float* ffn_out_W    = (const float*)d_in[13];
    const float* ffn_norm_w   = (const float*)d_in[14];
    const float* reward_norm_w= (const float*)d_in[15];
    const float* reward_W     = (const float*)d_in[16];
    const float* reward_b     = (const float*)d_in[17];
    const float* label_norm_w = (const float*)d_in[18];
    const float* label_W      = (const float*)d_in[19];
    const float* label_b      = (const float*)d_in[20];
    const float* box_norm_w   = (const float*)d_in[21];
    const float* boxh_W       = (const float*)d_in[22];
    const float* boxh_b       = (const float*)d_in[23];
    float* out = (float*)d_out;

    float *x, *hn, *qkv;
    float2* rope;
    __nv_bfloat16 *pwh,*pwl,*bwh,*bwl,*qkvWh,*qkvWl,*woh,*wol,*ghWh,*ghWl,*owh,*owl,*lwh,*lwl;
    __nv_bfloat16 *pah,*pal,*bsh,*bsl,*hnh,*hnl,*oah,*oal,*gsh,*gsl;
    { void* p;
      cudaGetSymbolAddress(&p, g_x);    x    = (float*)p;
      cudaGetSymbolAddress(&p, g_hn);   hn   = (float*)p;
      cudaGetSymbolAddress(&p, g_qkv);  qkv  = (float*)p;
      cudaGetSymbolAddress(&p, g_rope); rope = (float2*)p;
      cudaGetSymbolAddress(&p, g_pwh); pwh = (__nv_bfloat16*)p;
      cudaGetSymbolAddress(&p, g_pwl); pwl = (__nv_bfloat16*)p;
      cudaGetSymbolAddress(&p, g_bwh); bwh = (__nv_bfloat16*)p;
      cudaGetSymbolAddress(&p, g_bwl); bwl = (__nv_bfloat16*)p;
      cudaGetSymbolAddress(&p, g_qkvWh); qkvWh = (__nv_bfloat16*)p;
      cudaGetSymbolAddress(&p, g_qkvWl); qkvWl = (__nv_bfloat16*)p;
      cudaGetSymbolAddress(&p, g_woh); woh = (__nv_bfloat16*)p;
      cudaGetSymbolAddress(&p, g_wol); wol = (__nv_bfloat16*)p;
      cudaGetSymbolAddress(&p, g_ghWh); ghWh = (__nv_bfloat16*)p;
      cudaGetSymbolAddress(&p, g_ghWl); ghWl = (__nv_bfloat16*)p;
      cudaGetSymbolAddress(&p, g_owh); owh = (__nv_bfloat16*)p;
      cudaGetSymbolAddress(&p, g_owl); owl = (__nv_bfloat16*)p;
      cudaGetSymbolAddress(&p, g_lwh); lwh = (__nv_bfloat16*)p;
      cudaGetSymbolAddress(&p, g_lwl); lwl = (__nv_bfloat16*)p;
      cudaGetSymbolAddress(&p, g_pah); pah = (__nv_bfloat16*)p;
      cudaGetSymbolAddress(&p, g_pal); pal = (__nv_bfloat16*)p;
      cudaGetSymbolAddress(&p, g_bsh); bsh = (__nv_bfloat16*)p;
      cudaGetSymbolAddress(&p, g_bsl); bsl = (__nv_bfloat16*)p;
      cudaGetSymbolAddress(&p, g_hnh); hnh = (__nv_bfloat16*)p;
      cudaGetSymbolAddress(&p, g_hnl); hnl = (__nv_bfloat16*)p;
      cudaGetSymbolAddress(&p, g_oah); oah = (__nv_bfloat16*)p;
      cudaGetSymbolAddress(&p, g_oal); oal = (__nv_bfloat16*)p;
      cudaGetSymbolAddress(&p, g_gsh); gsh = (__nv_bfloat16*)p;
      cudaGetSymbolAddress(&p, g_gsl); gsl = (__nv_bfloat16*)p;
    }

    // dynamic smem opt-in for the BK=32 GEMM (82 KB)
    const int GSMEM = 2 * 2 * 20992;   // 83968
    cudaFuncSetAttribute(bf16_gemm_kernel<false,true, false>, cudaFuncAttributeMaxDynamicSharedMemorySize, GSMEM);
    cudaFuncSetAttribute(bf16_gemm_kernel<true, true, false>, cudaFuncAttributeMaxDynamicSharedMemorySize, GSMEM);
    cudaFuncSetAttribute(bf16_gemm_kernel<false,false,false>, cudaFuncAttributeMaxDynamicSharedMemorySize, GSMEM);
    cudaFuncSetAttribute(bf16_gemm_kernel<true, false,false>, cudaFuncAttributeMaxDynamicSharedMemorySize, GSMEM);
    cudaFuncSetAttribute(bf16_gemm_kernel<false,false,true >, cudaFuncAttributeMaxDynamicSharedMemorySize, GSMEM);

    // ---- conversions ----
    cvt_split_kernel<<<1024, 256>>>(patch_W, pwh, pwl, (size_t)D_MODEL*D_MODEL);
    cvt_split_kernel<<<1024, 256>>>(box_W,   bwh, bwl, (size_t)D_MODEL*D_MODEL);
    cvt_qkv_kernel<<<4096, 256>>>(Wq, Wk, Wv, qkvWh, qkvWl);
    cvt_split_kernel<<<2048, 256>>>(Wo, woh, wol, (size_t)WQKVO);
    cvt_gh_kernel<<<4096, 256>>>(gate_W, hidden_W, ghWh, ghWl);
    cvt_split_kernel<<<2048, 256>>>(ffn_out_W, owh, owl, (size_t)WFF);
    cvt_label_kernel<<<(D_MODEL*1024 + 255)/256, 256>>>(label_W, lwh, lwl);
    cvt_split_kernel<<<1024, 256>>>(patch, pah, pal, (size_t)ROWS*D_MODEL);
    rope_table_kernel<<<(SEQ*32 + 255)/256, 256>>>(rope);
    {
        int n = ROWS * 4 * 96;
        boxsin_kernel<<<(n + 255) / 256, 256>>>(box, bsh, bsl);
    }

    const dim3 m768 (D_MODEL/128, ROWS/128);
    const dim3 m2304(3*D_MODEL/128, ROWS/128);
    const dim3 m6144(2*DFF/128, ROWS/128);
    const dim3 m1024(1024/128, ROWS/128);

    // ---- Embedding ----
    bf16_gemm_kernel<false, true, false><<<m768, 256, GSMEM>>>(pah, pal, pwh, pwl, patch_b, x, nullptr, nullptr, ROWS, D_MODEL, D_MODEL, D_MODEL);
    bf16_gemm_kernel<true,  true, false><<<m768, 256, GSMEM>>>(bsh, bsl, bwh, bwl, box_b,   x, nullptr, nullptr, ROWS, D_MODEL, D_MODEL, D_MODEL);

    // ---- Layers ----
    for (int L = 0; L < NLAYERS; L++) {
        const size_t qoff = (size_t)L * D_MODEL * 3*D_MODEL;
        const size_t woff = (size_t)L * D_MODEL * D_MODEL;
        const size_t goff = (size_t)L * D_MODEL * 2*DFF;
        const size_t foff = (size_t)L * D_MODEL * DFF;
        const float* anw = attn_norm_w + (size_t)L * D_MODEL;
        const float* fnw = ffn_norm_w + (size_t)L * D_MODEL;

        // attention
        rmsnorm_kernel<<<ROWS, 256>>>(x, anw, (float*)nullptr, hnh, hnl);
        bf16_gemm_kernel<false, false, false><<<m2304, 256, GSMEM>>>(hnh, hnl, qkvWh + qoff, qkvWl + qoff, nullptr, qkv, nullptr, nullptr, ROWS, 3*D_MODEL, 3*D_MODEL, D_MODEL);
        flash_kernel<<<dim3(SEQ/64, BATCH*NH), 128>>>(qkv, rope, oah, oal);
        bf16_gemm_kernel<true, false, false><<<m768, 256, GSMEM>>>(oah, oal, woh + woff, wol + woff, nullptr, x, nullptr, nullptr, ROWS, D_MODEL, D_MODEL, D_MODEL);

        // FFN (silu fused into gh GEMM epilogue via interleaved columns)
        rmsnorm_kernel<<<ROWS, 256>>>(x, fnw, (float*)nullptr, hnh, hnl);
        bf16_gemm_kernel<false, false, true><<<m6144, 256, GSMEM>>>(hnh, hnl, ghWh + goff, ghWl + goff, nullptr, nullptr, gsh, gsl, ROWS, 2*DFF, 2*DFF, D_MODEL);
        bf16_gemm_kernel<true, false, false><<<m768, 256, GSMEM>>>(gsh, gsl, owh + foff, owl + foff, nullptr, x, nullptr, nullptr, ROWS, D_MODEL, D_MODEL, DFF);
    }

    // ---- Heads ----
    float* out_reward = out;
    float* out_label  = out + (size_t)ROWS * 2;
    float* out_box    = out + (size_t)ROWS * 2 + (size_t)ROWS * 1000;

    rmsnorm_kernel<<<ROWS, 256>>>(x, reward_norm_w, hn, (__nv_bfloat16*)nullptr, (__nv_bfloat16*)nullptr);
    gemm_kernel<false, true><<<dim3(1, ROWS/64), 256>>>(hn, reward_W, reward_b, out_reward, ROWS, 2, D_MODEL);

    rmsnorm_kernel<<<ROWS, 256>>>(x, label_norm_w, (float*)nullptr, hnh, hnl);
    bf16_gemm_kernel<false, true, false><<<m1024, 256, GSMEM>>>(hnh, hnl, lwh, lwl, label_b, out_label, nullptr, nullptr, ROWS, 1000, 1024, D_MODEL);

    rmsnorm_kernel<<<ROWS, 256>>>(x, box_norm_w, hn, (__nv_bfloat16*)nullptr, (__nv_bfloat16*)nullptr);
    gemm_kernel<false, true><<<dim3(1, ROWS/64), 256>>>(hn, boxh_W, boxh_b, out_box, ROWS, 4, D_MODEL);
}

// round 16
// speedup vs baseline: 1.2356x; 1.2356x over previous
#include <cuda_runtime.h>
#include <cuda_bf16.h>
#include <cuda_fp16.h>
#include <math.h>
#include <stdint.h>

#define D_MODEL 768
#define NH      12
#define DH      64
#define SEQ     512
#define BATCH   8
#define ROWS    (BATCH*SEQ)   /* 4096 */
#define DFF     3072
#define NLAYERS 12
#define LN1E4   9.210340371976184f
#define WQKVO   (NLAYERS*D_MODEL*D_MODEL)
#define WFF     (NLAYERS*D_MODEL*DFF)
#define WQKV3   (NLAYERS*D_MODEL*3*D_MODEL)
#define WGH2    (NLAYERS*D_MODEL*2*DFF)

// ----------------------------------------------------------------------------
// Scratch (device globals; no allocation anywhere)
// ----------------------------------------------------------------------------
__device__ float g_x   [ROWS*D_MODEL];
__device__ float g_hn  [ROWS*D_MODEL];
__device__ float g_qkv [ROWS*3*D_MODEL];          // fused QKV output (fp32)
__device__ float2 g_rope[SEQ*32];                 // (cos, sin) per (pos, pair)

// fp16 weight planes (single-rounded; error bounded by TF32 case), layout [K][N]
__device__ __half g_pw[D_MODEL*D_MODEL];
__device__ __half g_bw[D_MODEL*D_MODEL];
__device__ __half g_qkvW[WQKV3];                  // [L][768][2304] Q|K|V
__device__ __half g_woW[WQKVO];
__device__ __half g_ghW[WGH2];                    // [L][768][6144] INTERLEAVED g/h cols
__device__ __half g_owW[WFF];
__device__ __half g_lw[D_MODEL*1024];             // [768][1024] zero-padded
// fp16 hi/lo activation planes
__device__ __half g_pah[ROWS*D_MODEL], g_pal[ROWS*D_MODEL];
__device__ __half g_bsh[ROWS*D_MODEL], g_bsl[ROWS*D_MODEL];
__device__ __half g_hnh[ROWS*D_MODEL], g_hnl[ROWS*D_MODEL];
__device__ __half g_oah[ROWS*D_MODEL], g_oal[ROWS*D_MODEL];
__device__ __half g_gsh[ROWS*DFF],     g_gsl[ROWS*DFF];

// ----------------------------------------------------------------------------
// helpers
// ----------------------------------------------------------------------------
__device__ __forceinline__ uint32_t smem_u32(const void* p) {
    return (uint32_t)__cvta_generic_to_shared(p);
}
// fp16 hi/lo split (activations)
__device__ __forceinline__ void splith(float f, __half& h, __half& l) {
    h = __float2half_rn(f);
    l = __float2half_rn(f - __half2float(h));
}
__device__ __forceinline__ void split2h(float f0, float f1, uint32_t& hi, uint32_t& lo) {
    __half h0, l0, h1, l1;
    splith(f0, h0, l0); splith(f1, h1, l1);
    __half2 hp(h0, h1), lp(l0, l1);
    hi = *(uint32_t*)&hp; lo = *(uint32_t*)&lp;
}
// bf16 split (flash kernel internals, validated R10)
__device__ __forceinline__ void splitbf(float f, __nv_bfloat16& h, __nv_bfloat16& l) {
    h = __float2bfloat16_rn(f);
    l = __float2bfloat16_rn(f - __bfloat162float(h));
}
__device__ __forceinline__ void split2u(float f0, float f1, uint32_t& hi, uint32_t& lo) {
    __nv_bfloat16 h0, l0, h1, l1;
    splitbf(f0, h0, l0); splitbf(f1, h1, l1);
    __nv_bfloat162 hp(h0, h1), lp(l0, l1);
    hi = *(uint32_t*)&hp; lo = *(uint32_t*)&lp;
}
__device__ __forceinline__ void cp16(uint32_t dst, const void* src) {
    asm volatile("cp.async.cg.shared.global [%0], [%1], 16;" :: "r"(dst), "l"(src));
}
__device__ __forceinline__ void ldsm4(uint32_t r[4], uint32_t addr) {
    asm volatile("ldmatrix.sync.aligned.m8n8.x4.shared.b16 {%0,%1,%2,%3}, [%4];"
                 : "=r"(r[0]), "=r"(r[1]), "=r"(r[2]), "=r"(r[3]) : "r"(addr));
}
__device__ __forceinline__ void ldsm2(uint32_t r[2], uint32_t addr) {
    asm volatile("ldmatrix.sync.aligned.m8n8.x2.shared.b16 {%0,%1}, [%2];"
                 : "=r"(r[0]), "=r"(r[1]) : "r"(addr));
}
__device__ __forceinline__ void ldsm2t(uint32_t r[2], uint32_t addr) {
    asm volatile("ldmatrix.sync.aligned.m8n8.x2.trans.shared.b16 {%0,%1}, [%2];"
                 : "=r"(r[0]), "=r"(r[1]) : "r"(addr));
}
__device__ __forceinline__ void mma_f16(float c[4], const uint32_t a[4], const uint32_t b[2]) {
    asm volatile(
        "mma.sync.aligned.m16n8k16.row.col.f32.f16.f16.f32 "
        "{%0,%1,%2,%3}, {%4,%5,%6,%7}, {%8,%9}, {%0,%1,%2,%3};"
        : "+f"(c[0]), "+f"(c[1]), "+f"(c[2]), "+f"(c[3])
        : "r"(a[0]), "r"(a[1]), "r"(a[2]), "r"(a[3]), "r"(b[0]), "r"(b[1]));
}
__device__ __forceinline__ void mma_bf16(float c[4], const uint32_t a[4], const uint32_t b[2]) {
    asm volatile(
        "mma.sync.aligned.m16n8k16.row.col.f32.bf16.bf16.f32 "
        "{%0,%1,%2,%3}, {%4,%5,%6,%7}, {%8,%9}, {%0,%1,%2,%3};"
        : "+f"(c[0]), "+f"(c[1]), "+f"(c[2]), "+f"(c[3])
        : "r"(a[0]), "r"(a[1]), "r"(a[2]), "r"(a[3]), "r"(b[0]), "r"(b[1]));
}

// ----------------------------------------------------------------------------
// conversion kernels
// ----------------------------------------------------------------------------
// activations: fp32 -> fp16 hi/lo planes
__global__ void cvt_split_kernel(const float* __restrict__ in,
                                 __half* __restrict__ hi, __half* __restrict__ lo, size_t n)
{
    size_t stride = (size_t)gridDim.x * blockDim.x * 4;
    for (size_t i = ((size_t)blockIdx.x * blockDim.x + threadIdx.x) * 4; i < n; i += stride) {
        float4 v = *(const float4*)(in + i);
        uint32_t h01, l01, h23, l23;
        split2h(v.x, v.y, h01, l01);
        split2h(v.z, v.w, h23, l23);
        *(uint32_t*)(hi+i)   = h01; *(uint32_t*)(hi+i+2) = h23;
        *(uint32_t*)(lo+i)   = l01; *(uint32_t*)(lo+i+2) = l23;
    }
}
// weights: fp32 -> single fp16 plane
__global__ void cvt_w_kernel(const float* __restrict__ in, __half* __restrict__ w, size_t n)
{
    size_t stride = (size_t)gridDim.x * blockDim.x * 4;
    for (size_t i = ((size_t)blockIdx.x * blockDim.x + threadIdx.x) * 4; i < n; i += stride) {
        float4 v = *(const float4*)(in + i);
        __half2 p0(__float2half_rn(v.x), __float2half_rn(v.y));
        __half2 p1(__float2half_rn(v.z), __float2half_rn(v.w));
        *(__half2*)(w+i)   = p0;
        *(__half2*)(w+i+2) = p1;
    }
}
// QKV concat: out [L][768][2304]
__global__ void cvt_qkv_kernel(const float* __restrict__ Wq, const float* __restrict__ Wk,
                               const float* __restrict__ Wv, __half* __restrict__ w)
{
    size_t n4 = (size_t)WQKV3 / 4;
    size_t stride = (size_t)gridDim.x * blockDim.x;
    for (size_t i4 = (size_t)blockIdx.x * blockDim.x + threadIdx.x; i4 < n4; i4 += stride) {
        size_t i = i4 * 4;
        int col = (int)(i % 2304);
        size_t rl = i / 2304;
        int row = (int)(rl % D_MODEL);
        int layer = (int)(rl / D_MODEL);
        const float* src = (col < 768) ? Wq : ((col < 1536) ? Wk : Wv);
        size_t soff = (((size_t)layer * D_MODEL + row) * D_MODEL) + (col % 768);
        float4 v = *(const float4*)(src + soff);
        __half2 p0(__float2half_rn(v.x), __float2half_rn(v.y));
        __half2 p1(__float2half_rn(v.z), __float2half_rn(v.w));
        *(__half2*)(w+i)   = p0;
        *(__half2*)(w+i+2) = p1;
    }
}
// gate|hidden INTERLEAVED cols: out [L][768][6144], even col 2j = gate_j, odd = hidden_j
__global__ void cvt_gh_kernel(const float* __restrict__ Wg, const float* __restrict__ Wh,
                              __half* __restrict__ w)
{
    size_t n4 = (size_t)WGH2 / 4;
    size_t stride = (size_t)gridDim.x * blockDim.x;
    for (size_t i4 = (size_t)blockIdx.x * blockDim.x + threadIdx.x; i4 < n4; i4 += stride) {
        size_t i = i4 * 4;
        int col = (int)(i % 6144);
        size_t rl = i / 6144;
        int row = (int)(rl % D_MODEL);
        int layer = (int)(rl / D_MODEL);
        int j = col >> 1;
        size_t base = ((size_t)layer * D_MODEL + row) * DFF;
        float2 gv = *(const float2*)(Wg + base + j);
        float2 hv = *(const float2*)(Wh + base + j);
        __half2 p0(__float2half_rn(gv.x), __float2half_rn(hv.x));
        __half2 p1(__float2half_rn(gv.y), __float2half_rn(hv.y));
        *(__half2*)(w+i)   = p0;
        *(__half2*)(w+i+2) = p1;
    }
}
__global__ void cvt_label_kernel(const float* __restrict__ in, __half* __restrict__ w)
{
    int idx = blockIdx.x * blockDim.x + threadIdx.x;
    if (idx >= D_MODEL * 1024) return;
    int row = idx >> 10, col = idx & 1023;
    float v = (col < 1000) ? in[row * 1000 + col] : 0.f;
    w[idx] = __float2half_rn(v);
}
__global__ void rope_table_kernel(float2* __restrict__ t)
{
    int idx = blockIdx.x * blockDim.x + threadIdx.x;
    if (idx >= SEQ * 32) return;
    int j = idx & 31, l = idx >> 5;
    float theta = expf(-(float)j * (LN1E4 / 32.f));
    float s, c; sincosf((float)l * theta, &s, &c);
    t[idx] = make_float2(c, s);
}

// ----------------------------------------------------------------------------
// fp16x2 split GEMM (R12 pipeline): C = (Ah+Al) @ W, fp32 accum.
// A fp16 hi/lo [M][K]; W single fp16 [K][N]. Error bounded by TF32 (passed @9e-4).
// SILU=true: interleaved (gate,hidden) columns; writes silu(g)*h fp16 planes.
// ----------------------------------------------------------------------------
template<bool ACC, bool BIAS, bool SILU>
__global__ __launch_bounds__(256, 2)
void fp16_gemm_kernel(const __half* __restrict__ Ah, const __half* __restrict__ Al,
                      const __half* __restrict__ W,
                      const float* __restrict__ bias, float* __restrict__ C,
                      __half* __restrict__ Oh, __half* __restrict__ Ol,
                      int M, int N, int NB, int K)
{
    constexpr int A_HI = 0, A_LO = 6144, B_OF = 12288, STG = 16640;
    __shared__ __align__(128) uint8_t smem[2 * STG];

    const int tid  = threadIdx.x;
    const int lane = tid & 31;
    const int warp = tid >> 5;
    const int wm   = warp >> 2;
    const int wn   = warp & 3;
    const int grp  = lane >> 2;
    const int tg   = lane & 3;
    const int m0 = blockIdx.y * 128;
    const int n0 = blockIdx.x * 128;

    const int ar = tid >> 1;
    const int kr = tid >> 4;
    const __half* pAh = Ah + (size_t)(m0 + ar) * K + (tid & 1) * 8;
    const __half* pAl = Al + (size_t)(m0 + ar) * K + (tid & 1) * 8;
    const __half* pB  = W  + (size_t)kr * NB + n0 + (tid & 15) * 8;
    const uint32_t sb   = smem_u32(smem);
    const uint32_t adst = ar * 48 + (tid & 1) * 16;
    const uint32_t bdst = kr * 272 + (tid & 15) * 16;

    const int l16 = lane & 15;
    uint32_t aoff[4], boff[4];
    #pragma unroll
    for (int mt = 0; mt < 4; mt++)
        aoff[mt] = (uint32_t)((wm*64 + mt*16 + l16) * 48 + ((lane >> 4) & 1) * 16);
    #pragma unroll
    for (int nt = 0; nt < 4; nt++)
        boff[nt] = (uint32_t)(l16 * 272 + (wn*32 + nt*8) * 2);

    float acc[4][4][4];
    #pragma unroll
    for (int i = 0; i < 4; i++)
        #pragma unroll
        for (int j = 0; j < 4; j++)
            #pragma unroll
            for (int c = 0; c < 4; c++) acc[i][j][c] = 0.f;

    const int nk = K >> 4;
    {
        cp16(sb + A_HI + adst, pAh);
        cp16(sb + A_LO + adst, pAl);
        cp16(sb + B_OF + bdst, pB);
        asm volatile("cp.async.commit_group;" ::: "memory");
    }

    for (int kt = 0; kt < nk; kt++) {
        const int buf = kt & 1;
        if (kt + 1 < nk) {
            const uint32_t s = sb + (buf ^ 1) * STG;
            const size_t ka = (size_t)(kt + 1) * 16;
            cp16(s + A_HI + adst, pAh + ka);
            cp16(s + A_LO + adst, pAl + ka);
            cp16(s + B_OF + bdst, pB + ka * NB);
            asm volatile("cp.async.commit_group;" ::: "memory");
            asm volatile("cp.async.wait_group 1;" ::: "memory");
        } else {
            asm volatile("cp.async.wait_group 0;" ::: "memory");
        }
        __syncthreads();

        const uint32_t s = sb + buf * STG;
        uint32_t bh[4][2];
        #pragma unroll
        for (int nt = 0; nt < 4; nt++)
            ldsm2t(bh[nt], s + B_OF + boff[nt]);
        #pragma unroll
        for (int mt = 0; mt < 4; mt++) {
            uint32_t ah[4], al[4];
            ldsm4(ah, s + A_HI + aoff[mt]);
            ldsm4(al, s + A_LO + aoff[mt]);
            #pragma unroll
            for (int nt = 0; nt < 4; nt++) {
                mma_f16(acc[mt][nt], ah, bh[nt]);
                mma_f16(acc[mt][nt], al, bh[nt]);
            }
        }
        __syncthreads();
    }

    if (SILU) {
        #pragma unroll
        for (int mt = 0; mt < 4; mt++) {
            #pragma unroll
            for (int nt = 0; nt < 4; nt++) {
                int col  = n0 + wn*32 + nt*8 + tg*2;    // even
                int feat = col >> 1;
                int row0 = m0 + wm*64 + mt*16 + grp;
                {
                    float g = acc[mt][nt][0], hv = acc[mt][nt][1];
                    float r = (g / (1.f + expf(-g))) * hv;
                    __half hh, ll; splith(r, hh, ll);
                    size_t off = (size_t)row0 * DFF + feat;
                    Oh[off] = hh; Ol[off] = ll;
                }
                {
                    float g = acc[mt][nt][2], hv = acc[mt][nt][3];
                    float r = (g / (1.f + expf(-g))) * hv;
                    __half hh, ll; splith(r, hh, ll);
                    size_t off = (size_t)(row0 + 8) * DFF + feat;
                    Oh[off] = hh; Ol[off] = ll;
                }
            }
        }
    } else {
        #pragma unroll
        for (int mt = 0; mt < 4; mt++) {
            #pragma unroll
            for (int nt = 0; nt < 4; nt++) {
                #pragma unroll
                for (int c = 0; c < 4; c++) {
                    int row = m0 + wm*64 + mt*16 + grp + ((c >= 2) ? 8 : 0);
                    int col = n0 + wn*32 + nt*8 + tg*2 + (c & 1);
                    if (col < N) {
                        float v = acc[mt][nt][c];
                        if (BIAS) v += bias[col];
                        size_t off = (size_t)row * N + col;
                        if (ACC) v += C[off];
                        C[off] = v;
                    }
                }
            }
        }
    }
}

// ----------------------------------------------------------------------------
// Fused flash attention (validated R10 internals; fp16 output planes)
// ----------------------------------------------------------------------------
__global__ __launch_bounds__(128)
void flash_kernel(const float* __restrict__ qkv, const float2* __restrict__ rope,
                  __half* __restrict__ Oh, __half* __restrict__ Ol)
{
    __shared__ __nv_bfloat16 KS[2][64][72];
    __shared__ __nv_bfloat16 VS[2][64][72];

    const int mb = blockIdx.x;
    const int bh = blockIdx.y;
    const int b = bh / NH, h = bh % NH;
    const int tid = threadIdx.x, lane = tid & 31, w = tid >> 5;
    const int grp = lane >> 2, tg = lane & 3;
    const int l16 = lane & 15;

    const int srow = tid >> 1;
    const int sch  = (tid & 1) * 32;

    {
        int pos = mb*64 + srow;
        size_t base = ((size_t)(b*SEQ + pos)) * 2304 + h*DH + sch;
        #pragma unroll
        for (int p = 0; p < 16; p++) {
            int c = sch + 2*p;
            float2 qv = *(const float2*)(qkv + base + 2*p);
            float2 cs = rope[pos*32 + (c >> 1)];
            float xr = qv.x*cs.x - qv.y*cs.y;
            float xi = qv.x*cs.y + qv.y*cs.x;
            uint32_t hp, lp; split2u(xr, xi, hp, lp);
            *(uint32_t*)&KS[0][srow][c] = hp;
            *(uint32_t*)&KS[1][srow][c] = lp;
        }
    }
    __syncthreads();
    uint32_t Qa[4][2][4];
    #pragma unroll
    for (int k0 = 0; k0 < 4; k0++) {
        ldsm4(Qa[k0][0], smem_u32(&KS[0][w*16 + l16][k0*16 + ((lane >> 4) & 1)*8]));
        ldsm4(Qa[k0][1], smem_u32(&KS[1][w*16 + l16][k0*16 + ((lane >> 4) & 1)*8]));
    }
    __syncthreads();

    float O[8][4];
    #pragma unroll
    for (int dt = 0; dt < 8; dt++)
        #pragma unroll
        for (int c = 0; c < 4; c++) O[dt][c] = 0.f;
    float mrow[2] = {-1e30f, -1e30f};
    float lrow[2] = {0.f, 0.f};

    const int myrow0 = mb*64 + w*16 + grp;
    const int myrow1 = myrow0 + 8;

    for (int nb = 0; nb <= mb; nb++) {
        {
            int pos = nb*64 + srow;
            size_t kbase = ((size_t)(b*SEQ + pos)) * 2304 + 768 + h*DH + sch;
            #pragma unroll
            for (int p = 0; p < 16; p++) {
                int c = sch + 2*p;
                float2 kv = *(const float2*)(qkv + kbase + 2*p);
                float2 cs = rope[pos*32 + (c >> 1)];
                float xr = kv.x*cs.x - kv.y*cs.y;
                float xi = kv.x*cs.y + kv.y*cs.x;
                uint32_t hp, lp; split2u(xr, xi, hp, lp);
                *(uint32_t*)&KS[0][srow][c] = hp;
                *(uint32_t*)&KS[1][srow][c] = lp;
            }
            size_t vbase = kbase + 768;
            #pragma unroll
            for (int p = 0; p < 8; p++) {
                float4 vv = *(const float4*)(qkv + vbase + 4*p);
                int c = sch + 4*p;
                uint32_t h01, l01, h23, l23;
                split2u(vv.x, vv.y, h01, l01);
                split2u(vv.z, vv.w, h23, l23);
                *(uint32_t*)&VS[0][srow][c]   = h01;
                *(uint32_t*)&VS[0][srow][c+2] = h23;
                *(uint32_t*)&VS[1][srow][c]   = l01;
                *(uint32_t*)&VS[1][srow][c+2] = l23;
            }
        }
        __syncthreads();

        float S[8][4];
        #pragma unroll
        for (int nt = 0; nt < 8; nt++)
            #pragma unroll
            for (int c = 0; c < 4; c++) S[nt][c] = 0.f;
        #pragma unroll
        for (int k0 = 0; k0 < 4; k0++) {
            #pragma unroll
            for (int nt = 0; nt < 8; nt++) {
                uint32_t kh2[2], kl2[2];
                uint32_t kaddr_h = smem_u32(&KS[0][nt*8 + (l16 & 7)][k0*16 + ((l16 >> 3) & 1)*8]);
                uint32_t kaddr_l = smem_u32(&KS[1][nt*8 + (l16 & 7)][k0*16 + ((l16 >> 3) & 1)*8]);
                ldsm2(kh2, kaddr_h);
                ldsm2(kl2, kaddr_l);
                mma_bf16(S[nt], Qa[k0][0], kh2);
                mma_bf16(S[nt], Qa[k0][1], kh2);
                mma_bf16(S[nt], Qa[k0][0], kl2);
            }
        }
        #pragma unroll
        for (int nt = 0; nt < 8; nt++) {
            #pragma unroll
            for (int c = 0; c < 4; c++) {
                float v = S[nt][c] * 0.125f;
                if (nb == mb) {
                    int col = nb*64 + nt*8 + tg*2 + (c & 1);
                    int row = (c >= 2) ? myrow1 : myrow0;
                    if (col > row) v = -1e30f;
                }
                S[nt][c] = v;
            }
        }

        float mx0 = -1e30f, mx1 = -1e30f;
        #pragma unroll
        for (int nt = 0; nt < 8; nt++) {
            mx0 = fmaxf(mx0, fmaxf(S[nt][0], S[nt][1]));
            mx1 = fmaxf(mx1, fmaxf(S[nt][2], S[nt][3]));
        }
        mx0 = fmaxf(mx0, __shfl_xor_sync(0xffffffffu, mx0, 1));
        mx0 = fmaxf(mx0, __shfl_xor_sync(0xffffffffu, mx0, 2));
        mx1 = fmaxf(mx1, __shfl_xor_sync(0xffffffffu, mx1, 1));
        mx1 = fmaxf(mx1, __shfl_xor_sync(0xffffffffu, mx1, 2));
        float mn0 = fmaxf(mrow[0], mx0), mn1 = fmaxf(mrow[1], mx1);
        float sc0 = __expf(mrow[0] - mn0), sc1 = __expf(mrow[1] - mn1);
        float sum0 = 0.f, sum1 = 0.f;
        #pragma unroll
        for (int nt = 0; nt < 8; nt++) {
            S[nt][0] = __expf(S[nt][0] - mn0);
            S[nt][1] = __expf(S[nt][1] - mn0);
            S[nt][2] = __expf(S[nt][2] - mn1);
            S[nt][3] = __expf(S[nt][3] - mn1);
            sum0 += S[nt][0] + S[nt][1];
            sum1 += S[nt][2] + S[nt][3];
        }
        sum0 += __shfl_xor_sync(0xffffffffu, sum0, 1);
        sum0 += __shfl_xor_sync(0xffffffffu, sum0, 2);
        sum1 += __shfl_xor_sync(0xffffffffu, sum1, 1);
        sum1 += __shfl_xor_sync(0xffffffffu, sum1, 2);
        lrow[0] = lrow[0]*sc0 + sum0;
        lrow[1] = lrow[1]*sc1 + sum1;
        mrow[0] = mn0; mrow[1] = mn1;
        #pragma unroll
        for (int dt = 0; dt < 8; dt++) {
            O[dt][0] *= sc0; O[dt][1] *= sc0;
            O[dt][2] *= sc1; O[dt][3] *= sc1;
        }

        #pragma unroll
        for (int k0p = 0; k0p < 4; k0p++) {
            const int n0t = 2*k0p, n1t = 2*k0p + 1;
            uint32_t pah[4], pal[4];
            split2u(S[n0t][0], S[n0t][1], pah[0], pal[0]);
            split2u(S[n0t][2], S[n0t][3], pah[1], pal[1]);
            split2u(S[n1t][0], S[n1t][1], pah[2], pal[2]);
            split2u(S[n1t][2], S[n1t][3], pah[3], pal[3]);
            #pragma unroll
            for (int dt = 0; dt < 8; dt++) {
                uint32_t vh2[2], vl2[2];
                ldsm2t(vh2, smem_u32(&VS[0][k0p*16 + l16][dt*8]));
                ldsm2t(vl2, smem_u32(&VS[1][k0p*16 + l16][dt*8]));
                mma_bf16(O[dt], pah, vh2);
                mma_bf16(O[dt], pal, vh2);
                mma_bf16(O[dt], pah, vl2);
            }
        }
        __syncthreads();
    }

    float inv0 = 1.f / lrow[0], inv1 = 1.f / lrow[1];
    #pragma unroll
    for (int dt = 0; dt < 8; dt++) {
        #pragma unroll
        for (int c = 0; c < 4; c++) {
            int row = (c >= 2) ? myrow1 : myrow0;
            int col = h*DH + dt*8 + tg*2 + (c & 1);
            float v = O[dt][c] * ((c >= 2) ? inv1 : inv0);
            __half hh, ll; splith(v, hh, ll);
            size_t off = ((size_t)(b*SEQ + row)) * D_MODEL + col;
            Oh[off] = hh; Ol[off] = ll;
        }
    }
}

// ----------------------------------------------------------------------------
// Legacy SIMT SGEMM (tiny-N heads: N=2, N=4)
// ----------------------------------------------------------------------------
template<bool ACC, bool BIAS>
__global__ void gemm_kernel(const float* __restrict__ A, const float* __restrict__ B,
                            const float* __restrict__ bias, float* __restrict__ C,
                            int M, int N, int K)
{
    __shared__ float As[16][65];
    __shared__ float Bs[16][64];
    const int tid = threadIdx.x;
    const int tx = tid & 15, ty = tid >> 4;
    const int m0 = blockIdx.y * 64, n0 = blockIdx.x * 64;
    const int arow = tid >> 2, akk = (tid & 3) * 4;
    const int bkk = ty, bcol = tx * 4;

    float acc[4][4];
    #pragma unroll
    for (int i = 0; i < 4; i++)
        #pragma unroll
        for (int j = 0; j < 4; j++) acc[i][j] = 0.f;

    for (int k0 = 0; k0 < K; k0 += 16) {
        float4 av = *(const float4*)(A + (size_t)(m0 + arow) * K + k0 + akk);
        As[akk+0][arow] = av.x; As[akk+1][arow] = av.y;
        As[akk+2][arow] = av.z; As[akk+3][arow] = av.w;
        {
            int gn = n0 + bcol;
            const float* Bp = B + (size_t)(k0 + bkk) * N + gn;
            float4 bv;
            if (gn + 3 < N) bv = *(const float4*)Bp;
            else {
                bv.x = (gn+0 < N) ? Bp[0] : 0.f;
                bv.y = (gn+1 < N) ? Bp[1] : 0.f;
                bv.z = (gn+2 < N) ? Bp[2] : 0.f;
                bv.w = (gn+3 < N) ? Bp[3] : 0.f;
            }
            *(float4*)&Bs[bkk][bcol] = bv;
        }
        __syncthreads();
        #pragma unroll
        for (int kk = 0; kk < 16; kk++) {
            float a0 = As[kk][ty*4+0], a1 = As[kk][ty*4+1];
            float a2 = As[kk][ty*4+2], a3 = As[kk][ty*4+3];
            float4 bv = *(const float4*)&Bs[kk][tx*4];
            acc[0][0] += a0*bv.x; acc[0][1] += a0*bv.y; acc[0][2] += a0*bv.z; acc[0][3] += a0*bv.w;
            acc[1][0] += a1*bv.x; acc[1][1] += a1*bv.y; acc[1][2] += a1*bv.z; acc[1][3] += a1*bv.w;
            acc[2][0] += a2*bv.x; acc[2][1] += a2*bv.y; acc[2][2] += a2*bv.z; acc[2][3] += a2*bv.w;
            acc[3][0] += a3*bv.x; acc[3][1] += a3*bv.y; acc[3][2] += a3*bv.z; acc[3][3] += a3*bv.w;
        }
        __syncthreads();
    }
    #pragma unroll
    for (int i = 0; i < 4; i++) {
        int gm = m0 + ty*4 + i;
        #pragma unroll
        for (int j = 0; j < 4; j++) {
            int gn = n0 + tx*4 + j;
            if (gn < N) {
                float v = acc[i][j];
                if (BIAS) v += bias[gn];
                size_t off = (size_t)gm * N + gn;
                if (ACC) v += C[off];
                C[off] = v;
            }
        }
    }
}

// ----------------------------------------------------------------------------
// box Fourier features -> fp16 hi/lo planes
// ----------------------------------------------------------------------------
__global__ void boxsin_kernel(const float* __restrict__ box,
                              __half* __restrict__ h, __half* __restrict__ l)
{
    int idx = blockIdx.x * blockDim.x + threadIdx.x;     // ROWS*4*96
    if (idx >= ROWS*4*96) return;
    int j   = idx % 96;
    int i   = (idx / 96) & 3;
    int row = idx / 384;
    float theta = expf(-(float)j * (LN1E4 / 96.f));
    float ang = box[row*4 + i] * theta;
    float s, c;
    sincosf(ang, &s, &c);
    size_t off = (size_t)row*D_MODEL + i*192 + 2*j;
    __half hh, ll;
    splith(c, hh, ll); h[off] = hh;   l[off] = ll;
    splith(s, hh, ll); h[off+1] = hh; l[off+1] = ll;
}

// ----------------------------------------------------------------------------
// RMSNorm -> optional f32 out + optional fp16 hi/lo planes
// ----------------------------------------------------------------------------
__global__ void rmsnorm_kernel(const float* __restrict__ x, const float* __restrict__ w,
                               float* __restrict__ out,
                               __half* __restrict__ oh, __half* __restrict__ ol)
{
    __shared__ float red[256];
    int row = blockIdx.x;
    const float* xr = x + (size_t)row * D_MODEL;
    float s = 0.f;
    for (int i = threadIdx.x; i < D_MODEL; i += 256) { float v = xr[i]; s += v*v; }
    red[threadIdx.x] = s; __syncthreads();
    for (int off = 128; off > 0; off >>= 1) {
        if (threadIdx.x < off) red[threadIdx.x] += red[threadIdx.x + off];
        __syncthreads();
    }
    float inv = rsqrtf(red[0] / (float)D_MODEL + 1e-6f);
    for (int i = threadIdx.x; i < D_MODEL; i += 256) {
        float v = xr[i] * inv * w[i];
        if (out) out[(size_t)row * D_MODEL + i] = v;
        if (oh) {
            __half hh, ll; splith(v, hh, ll);
            oh[(size_t)row * D_MODEL + i] = hh;
            ol[(size_t)row * D_MODEL + i] = ll;
        }
    }
}

// ----------------------------------------------------------------------------
// Launch
// ----------------------------------------------------------------------------
extern "C" void kernel_launch(void* const* d_in, const int* in_sizes, int n_in,
                              void* d_out, int out_size)
{
    const float* patch        = (const float*)d_in[0];
    const float* box          = (const float*)d_in[1];
    const float* patch_W      = (const float*)d_in[2];
    const float* patch_b      = (const float*)d_in[3];
    const float* box_W        = (const float*)d_in[4];
    const float* box_b        = (const float*)d_in[5];
    const float* Wq           = (const float*)d_in[6];
    const float* Wk           = (const float*)d_in[7];
    const float* Wv           = (const float*)d_in[8];
    const float* Wo           = (const float*)d_in[9];
    const float* attn_norm_w  = (const float*)d_in[10];
    const float* gate_W       = (const float*)d_in[11];
    const float* hidden_W     = (const float*)d_in[12];
    const float* ffn_out_W    = (const float*)d_in[13];
    const float* ffn_norm_w   = (const float*)d_in[14];
    const float* reward_norm_w= (const float*)d_in[15];
    const float* reward_W     = (const float*)d_in[16];
    const float* reward_b     = (const float*)d_in[17];
    const float* label_norm_w = (const float*)d_in[18];
    const float* label_W      = (const float*)d_in[19];
    const float* label_b      = (const float*)d_in[20];
    const float* box_norm_w   = (const float*)d_in[21];
    const float* boxh_W       = (const float*)d_in[22];
    const float* boxh_b       = (const float*)d_in[23];
    float* out = (float*)d_out;

    float *x, *hn, *qkv;
    float2* rope;
    __half *pw,*bw,*qkvW,*woW,*ghW,*owW,*lw;
    __half *pah,*pal,*bsh,*bsl,*hnh,*hnl,*oah,*oal,*gsh,*gsl;
    { void* p;
      cudaGetSymbolAddress(&p, g_x);    x    = (float*)p;
      cudaGetSymbolAddress(&p, g_hn);   hn   = (float*)p;
      cudaGetSymbolAddress(&p, g_qkv);  qkv  = (float*)p;
      cudaGetSymbolAddress(&p, g_rope); rope = (float2*)p;
      cudaGetSymbolAddress(&p, g_pw);   pw   = (__half*)p;
      cudaGetSymbolAddress(&p, g_bw);   bw   = (__half*)p;
      cudaGetSymbolAddress(&p, g_qkvW); qkvW = (__half*)p;
      cudaGetSymbolAddress(&p, g_woW);  woW  = (__half*)p;
      cudaGetSymbolAddress(&p, g_ghW);  ghW  = (__half*)p;
      cudaGetSymbolAddress(&p, g_owW);  owW  = (__half*)p;
      cudaGetSymbolAddress(&p, g_lw);   lw   = (__half*)p;
      cudaGetSymbolAddress(&p, g_pah);  pah  = (__half*)p;
      cudaGetSymbolAddress(&p, g_pal);  pal  = (__half*)p;
      cudaGetSymbolAddress(&p, g_bsh);  bsh  = (__half*)p;
      cudaGetSymbolAddress(&p, g_bsl);  bsl  = (__half*)p;
      cudaGetSymbolAddress(&p, g_hnh);  hnh  = (__half*)p;
      cudaGetSymbolAddress(&p, g_hnl);  hnl  = (__half*)p;
      cudaGetSymbolAddress(&p, g_oah);  oah  = (__half*)p;
      cudaGetSymbolAddress(&p, g_oal);  oal  = (__half*)p;
      cudaGetSymbolAddress(&p, g_gsh);  gsh  = (__half*)p;
      cudaGetSymbolAddress(&p, g_gsl);  gsl  = (__half*)p;
    }

    const dim3 m768 (D_MODEL/128, ROWS/128);
    const dim3 m2304(3*D_MODEL/128, ROWS/128);
    const dim3 m6144(2*DFF/128, ROWS/128);
    const dim3 m1024(1024/128, ROWS/128);

    // ---- conversions, ordered so launch #6 (ncu -s 5 -c 1) is the embed GEMM ----
    rope_table_kernel<<<(SEQ*32 + 255)/256, 256>>>(rope);                        // 1
    {
        int n = ROWS * 4 * 96;
        boxsin_kernel<<<(n + 255) / 256, 256>>>(box, bsh, bsl);                  // 2
    }
    cvt_split_kernel<<<1024, 256>>>(patch, pah, pal, (size_t)ROWS*D_MODEL);      // 3
    cvt_w_kernel<<<1024, 256>>>(patch_W, pw, (size_t)D_MODEL*D_MODEL);           // 4
    cvt_w_kernel<<<1024, 256>>>(box_W,   bw, (size_t)D_MODEL*D_MODEL);           // 5
    // ---- Embedding (launch #6: profiled GEMM) ----
    fp16_gemm_kernel<false, true, false><<<m768, 256>>>(pah, pal, pw, patch_b, x, nullptr, nullptr, ROWS, D_MODEL, D_MODEL, D_MODEL);   // 6
    fp16_gemm_kernel<true,  true, false><<<m768, 256>>>(bsh, bsl, bw, box_b,   x, nullptr, nullptr, ROWS, D_MODEL, D_MODEL, D_MODEL);   // 7
    // remaining weight conversions
    cvt_qkv_kernel<<<4096, 256>>>(Wq, Wk, Wv, qkvW);
    cvt_w_kernel<<<2048, 256>>>(Wo, woW, (size_t)WQKVO);
    cvt_gh_kernel<<<4096, 256>>>(gate_W, hidden_W, ghW);
    cvt_w_kernel<<<2048, 256>>>(ffn_out_W, owW, (size_t)WFF);
    cvt_label_kernel<<<(D_MODEL*1024 + 255)/256, 256>>>(label_W, lw);

    // ---- Layers ----
    for (int L = 0; L < NLAYERS; L++) {
        const size_t qoff = (size_t)L * D_MODEL * 3*D_MODEL;
        const size_t woff = (size_t)L * D_MODEL * D_MODEL;
        const size_t goff = (size_t)L * D_MODEL * 2*DFF;
        const size_t foff = (size_t)L * D_MODEL * DFF;
        const float* anw = attn_norm_w + (size_t)L * D_MODEL;
        const float* fnw = ffn_norm_w + (size_t)L * D_MODEL;

        // attention
        rmsnorm_kernel<<<ROWS, 256>>>(x, anw, (float*)nullptr, hnh, hnl);
        fp16_gemm_kernel<false, false, false><<<m2304, 256>>>(hnh, hnl, qkvW + qoff, nullptr, qkv, nullptr, nullptr, ROWS, 3*D_MODEL, 3*D_MODEL, D_MODEL);
        flash_kernel<<<dim3(SEQ/64, BATCH*NH), 128>>>(qkv, rope, oah, oal);
        fp16_gemm_kernel<true, false, false><<<m768, 256>>>(oah, oal, woW + woff, nullptr, x, nullptr, nullptr, ROWS, D_MODEL, D_MODEL, D_MODEL);

        // FFN (silu fused into gh GEMM epilogue via interleaved columns)
        rmsnorm_kernel<<<ROWS, 256>>>(x, fnw, (float*)nullptr, hnh, hnl);
        fp16_gemm_kernel<false, false, true><<<m6144, 256>>>(hnh, hnl, ghW + goff, nullptr, nullptr, gsh, gsl, ROWS, 2*DFF, 2*DFF, D_MODEL);
        fp16_gemm_kernel<true, false, false><<<m768, 256>>>(gsh, gsl, owW + foff, nullptr, x, nullptr, nullptr, ROWS, D_MODEL, D_MODEL, DFF);
    }

    // ---- Heads ----
    float* out_reward = out;
    float* out_label  = out + (size_t)ROWS * 2;
    float* out_box    = out + (size_t)ROWS * 2 + (size_t)ROWS * 1000;

    rmsnorm_kernel<<<ROWS, 256>>>(x, reward_norm_w, hn, (__half*)nullptr, (__half*)nullptr);
    gemm_kernel<false, true><<<dim3(1, ROWS/64), 256>>>(hn, reward_W, reward_b, out_reward, ROWS, 2, D_MODEL);

    rmsnorm_kernel<<<ROWS, 256>>>(x, label_norm_w, (float*)nullptr, hnh, hnl);
    fp16_gemm_kernel<false, true, false><<<m1024, 256>>>(hnh, hnl, lw, label_b, out_label, nullptr, nullptr, ROWS, 1000, 1024, D_MODEL);

    rmsnorm_kernel<<<ROWS, 256>>>(x, box_norm_w, hn, (__half*)nullptr, (__half*)nullptr);
    gemm_kernel<false, true><<<dim3(1, ROWS/64), 256>>>(hn, boxh_W, boxh_b, out_box, ROWS, 4, D_MODEL);
}

// round 17
// speedup vs baseline: 1.6511x; 1.3363x over previous
#include <cuda_runtime.h>
#include <cuda_bf16.h>
#include <cuda_fp16.h>
#include <math.h>
#include <stdint.h>

#define D_MODEL 768
#define NH      12
#define DH      64
#define SEQ     512
#define BATCH   8
#define ROWS    (BATCH*SEQ)   /* 4096 */
#define DFF     3072
#define NLAYERS 12
#define LN1E4   9.210340371976184f
#define WQKVO   (NLAYERS*D_MODEL*D_MODEL)
#define WFF     (NLAYERS*D_MODEL*DFF)
#define WQKV3   (NLAYERS*D_MODEL*3*D_MODEL)
#define WGH2    (NLAYERS*D_MODEL*2*DFF)

// ----------------------------------------------------------------------------
// Scratch (device globals; no allocation anywhere)
// ----------------------------------------------------------------------------
__device__ float g_x   [ROWS*D_MODEL];
__device__ float g_hn  [ROWS*D_MODEL];
__device__ float g_qkv [ROWS*3*D_MODEL];          // fused QKV output (fp32)
__device__ float2 g_rope[SEQ*32];                 // (cos, sin) per (pos, pair)

// fp16 weight planes (single-rounded; error bounded by TF32 case), layout [K][N]
__device__ __half g_pw[D_MODEL*D_MODEL];
__device__ __half g_bw[D_MODEL*D_MODEL];
__device__ __half g_qkvW[WQKV3];                  // [L][768][2304] Q|K|V
__device__ __half g_woW[WQKVO];
__device__ __half g_ghW[WGH2];                    // [L][768][6144] INTERLEAVED g/h cols
__device__ __half g_owW[WFF];
__device__ __half g_lw[D_MODEL*1024];             // [768][1024] zero-padded
// fp16 hi/lo activation planes
__device__ __half g_pah[ROWS*D_MODEL], g_pal[ROWS*D_MODEL];
__device__ __half g_bsh[ROWS*D_MODEL], g_bsl[ROWS*D_MODEL];
__device__ __half g_hnh[ROWS*D_MODEL], g_hnl[ROWS*D_MODEL];
__device__ __half g_oah[ROWS*D_MODEL], g_oal[ROWS*D_MODEL];
__device__ __half g_gsh[ROWS*DFF];                // FFN act: single plane (TF32-equiv path)

// ----------------------------------------------------------------------------
// helpers
// ----------------------------------------------------------------------------
__device__ __forceinline__ uint32_t smem_u32(const void* p) {
    return (uint32_t)__cvta_generic_to_shared(p);
}
// fp16 hi/lo split (activations)
__device__ __forceinline__ void splith(float f, __half& h, __half& l) {
    h = __float2half_rn(f);
    l = __float2half_rn(f - __half2float(h));
}
__device__ __forceinline__ void split2h(float f0, float f1, uint32_t& hi, uint32_t& lo) {
    __half h0, l0, h1, l1;
    splith(f0, h0, l0); splith(f1, h1, l1);
    __half2 hp(h0, h1), lp(l0, l1);
    hi = *(uint32_t*)&hp; lo = *(uint32_t*)&lp;
}
// bf16 split (flash kernel internals, validated R10)
__device__ __forceinline__ void splitbf(float f, __nv_bfloat16& h, __nv_bfloat16& l) {
    h = __float2bfloat16_rn(f);
    l = __float2bfloat16_rn(f - __bfloat162float(h));
}
__device__ __forceinline__ void split2u(float f0, float f1, uint32_t& hi, uint32_t& lo) {
    __nv_bfloat16 h0, l0, h1, l1;
    splitbf(f0, h0, l0); splitbf(f1, h1, l1);
    __nv_bfloat162 hp(h0, h1), lp(l0, l1);
    hi = *(uint32_t*)&hp; lo = *(uint32_t*)&lp;
}
__device__ __forceinline__ void cp16(uint32_t dst, const void* src) {
    asm volatile("cp.async.cg.shared.global [%0], [%1], 16;" :: "r"(dst), "l"(src));
}
__device__ __forceinline__ void ldsm4(uint32_t r[4], uint32_t addr) {
    asm volatile("ldmatrix.sync.aligned.m8n8.x4.shared.b16 {%0,%1,%2,%3}, [%4];"
                 : "=r"(r[0]), "=r"(r[1]), "=r"(r[2]), "=r"(r[3]) : "r"(addr));
}
__device__ __forceinline__ void ldsm2(uint32_t r[2], uint32_t addr) {
    asm volatile("ldmatrix.sync.aligned.m8n8.x2.shared.b16 {%0,%1}, [%2];"
                 : "=r"(r[0]), "=r"(r[1]) : "r"(addr));
}
__device__ __forceinline__ void ldsm2t(uint32_t r[2], uint32_t addr) {
    asm volatile("ldmatrix.sync.aligned.m8n8.x2.trans.shared.b16 {%0,%1}, [%2];"
                 : "=r"(r[0]), "=r"(r[1]) : "r"(addr));
}
__device__ __forceinline__ void mma_f16(float c[4], const uint32_t a[4], const uint32_t b[2]) {
    asm volatile(
        "mma.sync.aligned.m16n8k16.row.col.f32.f16.f16.f32 "
        "{%0,%1,%2,%3}, {%4,%5,%6,%7}, {%8,%9}, {%0,%1,%2,%3};"
        : "+f"(c[0]), "+f"(c[1]), "+f"(c[2]), "+f"(c[3])
        : "r"(a[0]), "r"(a[1]), "r"(a[2]), "r"(a[3]), "r"(b[0]), "r"(b[1]));
}
__device__ __forceinline__ void mma_bf16(float c[4], const uint32_t a[4], const uint32_t b[2]) {
    asm volatile(
        "mma.sync.aligned.m16n8k16.row.col.f32.bf16.bf16.f32 "
        "{%0,%1,%2,%3}, {%4,%5,%6,%7}, {%8,%9}, {%0,%1,%2,%3};"
        : "+f"(c[0]), "+f"(c[1]), "+f"(c[2]), "+f"(c[3])
        : "r"(a[0]), "r"(a[1]), "r"(a[2]), "r"(a[3]), "r"(b[0]), "r"(b[1]));
}

// ----------------------------------------------------------------------------
// conversion kernels
// ----------------------------------------------------------------------------
__global__ void cvt_split_kernel(const float* __restrict__ in,
                                 __half* __restrict__ hi, __half* __restrict__ lo, size_t n)
{
    size_t stride = (size_t)gridDim.x * blockDim.x * 4;
    for (size_t i = ((size_t)blockIdx.x * blockDim.x + threadIdx.x) * 4; i < n; i += stride) {
        float4 v = *(const float4*)(in + i);
        uint32_t h01, l01, h23, l23;
        split2h(v.x, v.y, h01, l01);
        split2h(v.z, v.w, h23, l23);
        *(uint32_t*)(hi+i)   = h01; *(uint32_t*)(hi+i+2) = h23;
        *(uint32_t*)(lo+i)   = l01; *(uint32_t*)(lo+i+2) = l23;
    }
}
__global__ void cvt_w_kernel(const float* __restrict__ in, __half* __restrict__ w, size_t n)
{
    size_t stride = (size_t)gridDim.x * blockDim.x * 4;
    for (size_t i = ((size_t)blockIdx.x * blockDim.x + threadIdx.x) * 4; i < n; i += stride) {
        float4 v = *(const float4*)(in + i);
        __half2 p0(__float2half_rn(v.x), __float2half_rn(v.y));
        __half2 p1(__float2half_rn(v.z), __float2half_rn(v.w));
        *(__half2*)(w+i)   = p0;
        *(__half2*)(w+i+2) = p1;
    }
}
__global__ void cvt_qkv_kernel(const float* __restrict__ Wq, const float* __restrict__ Wk,
                               const float* __restrict__ Wv, __half* __restrict__ w)
{
    size_t n4 = (size_t)WQKV3 / 4;
    size_t stride = (size_t)gridDim.x * blockDim.x;
    for (size_t i4 = (size_t)blockIdx.x * blockDim.x + threadIdx.x; i4 < n4; i4 += stride) {
        size_t i = i4 * 4;
        int col = (int)(i % 2304);
        size_t rl = i / 2304;
        int row = (int)(rl % D_MODEL);
        int layer = (int)(rl / D_MODEL);
        const float* src = (col < 768) ? Wq : ((col < 1536) ? Wk : Wv);
        size_t soff = (((size_t)layer * D_MODEL + row) * D_MODEL) + (col % 768);
        float4 v = *(const float4*)(src + soff);
        __half2 p0(__float2half_rn(v.x), __float2half_rn(v.y));
        __half2 p1(__float2half_rn(v.z), __float2half_rn(v.w));
        *(__half2*)(w+i)   = p0;
        *(__half2*)(w+i+2) = p1;
    }
}
__global__ void cvt_gh_kernel(const float* __restrict__ Wg, const float* __restrict__ Wh,
                              __half* __restrict__ w)
{
    size_t n4 = (size_t)WGH2 / 4;
    size_t stride = (size_t)gridDim.x * blockDim.x;
    for (size_t i4 = (size_t)blockIdx.x * blockDim.x + threadIdx.x; i4 < n4; i4 += stride) {
        size_t i = i4 * 4;
        int col = (int)(i % 6144);
        size_t rl = i / 6144;
        int row = (int)(rl % D_MODEL);
        int layer = (int)(rl / D_MODEL);
        int j = col >> 1;
        size_t base = ((size_t)layer * D_MODEL + row) * DFF;
        float2 gv = *(const float2*)(Wg + base + j);
        float2 hv = *(const float2*)(Wh + base + j);
        __half2 p0(__float2half_rn(gv.x), __float2half_rn(hv.x));
        __half2 p1(__float2half_rn(gv.y), __float2half_rn(hv.y));
        *(__half2*)(w+i)   = p0;
        *(__half2*)(w+i+2) = p1;
    }
}
__global__ void cvt_label_kernel(const float* __restrict__ in, __half* __restrict__ w)
{
    int idx = blockIdx.x * blockDim.x + threadIdx.x;
    if (idx >= D_MODEL * 1024) return;
    int row = idx >> 10, col = idx & 1023;
    float v = (col < 1000) ? in[row * 1000 + col] : 0.f;
    w[idx] = __float2half_rn(v);
}
__global__ void rope_table_kernel(float2* __restrict__ t)
{
    int idx = blockIdx.x * blockDim.x + threadIdx.x;
    if (idx >= SEQ * 32) return;
    int j = idx & 31, l = idx >> 5;
    float theta = expf(-(float)j * (LN1E4 / 32.f));
    float s, c; sincosf((float)l * theta, &s, &c);
    t[idx] = make_float2(c, s);
}

// ----------------------------------------------------------------------------
// fp16 split GEMM (R16 pipeline): C = (Ah [+ Al]) @ W, fp32 accum.
// TWO=true: A hi/lo (2 MMAs/frag, error < TF32). TWO=false: single A (TF32-equiv).
// SILU=true: interleaved (gate,hidden) cols; writes silu(g)*h fp16 plane(s).
// ----------------------------------------------------------------------------
template<bool ACC, bool BIAS, bool SILU, bool TWO>
__global__ __launch_bounds__(256, 2)
void fp16_gemm_kernel(const __half* __restrict__ Ah, const __half* __restrict__ Al,
                      const __half* __restrict__ W,
                      const float* __restrict__ bias, float* __restrict__ C,
                      __half* __restrict__ Oh, __half* __restrict__ Ol,
                      int M, int N, int NB, int K)
{
    constexpr int A_HI = 0, A_LO = 6144, B_OF = 12288, STG = 16640;
    __shared__ __align__(128) uint8_t smem[2 * STG];

    const int tid  = threadIdx.x;
    const int lane = tid & 31;
    const int warp = tid >> 5;
    const int wm   = warp >> 2;
    const int wn   = warp & 3;
    const int grp  = lane >> 2;
    const int tg   = lane & 3;
    const int m0 = blockIdx.y * 128;
    const int n0 = blockIdx.x * 128;

    const int ar = tid >> 1;
    const int kr = tid >> 4;
    const __half* pAh = Ah + (size_t)(m0 + ar) * K + (tid & 1) * 8;
    const __half* pAl = TWO ? (Al + (size_t)(m0 + ar) * K + (tid & 1) * 8) : nullptr;
    const __half* pB  = W  + (size_t)kr * NB + n0 + (tid & 15) * 8;
    const uint32_t sb   = smem_u32(smem);
    const uint32_t adst = ar * 48 + (tid & 1) * 16;
    const uint32_t bdst = kr * 272 + (tid & 15) * 16;

    const int l16 = lane & 15;
    uint32_t aoff[4], boff[4];
    #pragma unroll
    for (int mt = 0; mt < 4; mt++)
        aoff[mt] = (uint32_t)((wm*64 + mt*16 + l16) * 48 + ((lane >> 4) & 1) * 16);
    #pragma unroll
    for (int nt = 0; nt < 4; nt++)
        boff[nt] = (uint32_t)(l16 * 272 + (wn*32 + nt*8) * 2);

    float acc[4][4][4];
    #pragma unroll
    for (int i = 0; i < 4; i++)
        #pragma unroll
        for (int j = 0; j < 4; j++)
            #pragma unroll
            for (int c = 0; c < 4; c++) acc[i][j][c] = 0.f;

    const int nk = K >> 4;
    {
        cp16(sb + A_HI + adst, pAh);
        if (TWO) cp16(sb + A_LO + adst, pAl);
        cp16(sb + B_OF + bdst, pB);
        asm volatile("cp.async.commit_group;" ::: "memory");
    }

    for (int kt = 0; kt < nk; kt++) {
        const int buf = kt & 1;
        if (kt + 1 < nk) {
            const uint32_t s = sb + (buf ^ 1) * STG;
            const size_t ka = (size_t)(kt + 1) * 16;
            cp16(s + A_HI + adst, pAh + ka);
            if (TWO) cp16(s + A_LO + adst, pAl + ka);
            cp16(s + B_OF + bdst, pB + ka * NB);
            asm volatile("cp.async.commit_group;" ::: "memory");
            asm volatile("cp.async.wait_group 1;" ::: "memory");
        } else {
            asm volatile("cp.async.wait_group 0;" ::: "memory");
        }
        __syncthreads();

        const uint32_t s = sb + buf * STG;
        uint32_t bh[4][2];
        #pragma unroll
        for (int nt = 0; nt < 4; nt++)
            ldsm2t(bh[nt], s + B_OF + boff[nt]);
        #pragma unroll
        for (int mt = 0; mt < 4; mt++) {
            uint32_t ah[4], al[4];
            ldsm4(ah, s + A_HI + aoff[mt]);
            if (TWO) ldsm4(al, s + A_LO + aoff[mt]);
            #pragma unroll
            for (int nt = 0; nt < 4; nt++) {
                mma_f16(acc[mt][nt], ah, bh[nt]);
                if (TWO) mma_f16(acc[mt][nt], al, bh[nt]);
            }
        }
        __syncthreads();
    }

    if (SILU) {
        #pragma unroll
        for (int mt = 0; mt < 4; mt++) {
            #pragma unroll
            for (int nt = 0; nt < 4; nt++) {
                int col  = n0 + wn*32 + nt*8 + tg*2;    // even
                int feat = col >> 1;
                int row0 = m0 + wm*64 + mt*16 + grp;
                {
                    float g = acc[mt][nt][0], hv = acc[mt][nt][1];
                    float r = (g / (1.f + expf(-g))) * hv;
                    size_t off = (size_t)row0 * DFF + feat;
                    if (Ol) { __half hh, ll; splith(r, hh, ll); Oh[off] = hh; Ol[off] = ll; }
                    else    { Oh[off] = __float2half_rn(r); }
                }
                {
                    float g = acc[mt][nt][2], hv = acc[mt][nt][3];
                    float r = (g / (1.f + expf(-g))) * hv;
                    size_t off = (size_t)(row0 + 8) * DFF + feat;
                    if (Ol) { __half hh, ll; splith(r, hh, ll); Oh[off] = hh; Ol[off] = ll; }
                    else    { Oh[off] = __float2half_rn(r); }
                }
            }
        }
    } else {
        #pragma unroll
        for (int mt = 0; mt < 4; mt++) {
            #pragma unroll
            for (int nt = 0; nt < 4; nt++) {
                #pragma unroll
                for (int c = 0; c < 4; c++) {
                    int row = m0 + wm*64 + mt*16 + grp + ((c >= 2) ? 8 : 0);
                    int col = n0 + wn*32 + nt*8 + tg*2 + (c & 1);
                    if (col < N) {
                        float v = acc[mt][nt][c];
                        if (BIAS) v += bias[col];
                        size_t off = (size_t)row * N + col;
                        if (ACC) v += C[off];
                        C[off] = v;
                    }
                }
            }
        }
    }
}

// ----------------------------------------------------------------------------
// Fused flash attention (validated R10 internals; fp16 output planes)
// ----------------------------------------------------------------------------
__global__ __launch_bounds__(128)
void flash_kernel(const float* __restrict__ qkv, const float2* __restrict__ rope,
                  __half* __restrict__ Oh, __half* __restrict__ Ol)
{
    __shared__ __nv_bfloat16 KS[2][64][72];
    __shared__ __nv_bfloat16 VS[2][64][72];

    const int mb = blockIdx.x;
    const int bh = blockIdx.y;
    const int b = bh / NH, h = bh % NH;
    const int tid = threadIdx.x, lane = tid & 31, w = tid >> 5;
    const int grp = lane >> 2, tg = lane & 3;
    const int l16 = lane & 15;

    const int srow = tid >> 1;
    const int sch  = (tid & 1) * 32;

    {
        int pos = mb*64 + srow;
        size_t base = ((size_t)(b*SEQ + pos)) * 2304 + h*DH + sch;
        #pragma unroll
        for (int p = 0; p < 16; p++) {
            int c = sch + 2*p;
            float2 qv = *(const float2*)(qkv + base + 2*p);
            float2 cs = rope[pos*32 + (c >> 1)];
            float xr = qv.x*cs.x - qv.y*cs.y;
            float xi = qv.x*cs.y + qv.y*cs.x;
            uint32_t hp, lp; split2u(xr, xi, hp, lp);
            *(uint32_t*)&KS[0][srow][c] = hp;
            *(uint32_t*)&KS[1][srow][c] = lp;
        }
    }
    __syncthreads();
    uint32_t Qa[4][2][4];
    #pragma unroll
    for (int k0 = 0; k0 < 4; k0++) {
        ldsm4(Qa[k0][0], smem_u32(&KS[0][w*16 + l16][k0*16 + ((lane >> 4) & 1)*8]));
        ldsm4(Qa[k0][1], smem_u32(&KS[1][w*16 + l16][k0*16 + ((lane >> 4) & 1)*8]));
    }
    __syncthreads();

    float O[8][4];
    #pragma unroll
    for (int dt = 0; dt < 8; dt++)
        #pragma unroll
        for (int c = 0; c < 4; c++) O[dt][c] = 0.f;
    float mrow[2] = {-1e30f, -1e30f};
    float lrow[2] = {0.f, 0.f};

    const int myrow0 = mb*64 + w*16 + grp;
    const int myrow1 = myrow0 + 8;

    for (int nb = 0; nb <= mb; nb++) {
        {
            int pos = nb*64 + srow;
            size_t kbase = ((size_t)(b*SEQ + pos)) * 2304 + 768 + h*DH + sch;
            #pragma unroll
            for (int p = 0; p < 16; p++) {
                int c = sch + 2*p;
                float2 kv = *(const float2*)(qkv + kbase + 2*p);
                float2 cs = rope[pos*32 + (c >> 1)];
                float xr = kv.x*cs.x - kv.y*cs.y;
                float xi = kv.x*cs.y + kv.y*cs.x;
                uint32_t hp, lp; split2u(xr, xi, hp, lp);
                *(uint32_t*)&KS[0][srow][c] = hp;
                *(uint32_t*)&KS[1][srow][c] = lp;
            }
            size_t vbase = kbase + 768;
            #pragma unroll
            for (int p = 0; p < 8; p++) {
                float4 vv = *(const float4*)(qkv + vbase + 4*p);
                int c = sch + 4*p;
                uint32_t h01, l01, h23, l23;
                split2u(vv.x, vv.y, h01, l01);
                split2u(vv.z, vv.w, h23, l23);
                *(uint32_t*)&VS[0][srow][c]   = h01;
                *(uint32_t*)&VS[0][srow][c+2] = h23;
                *(uint32_t*)&VS[1][srow][c]   = l01;
                *(uint32_t*)&VS[1][srow][c+2] = l23;
            }
        }
        __syncthreads();

        float S[8][4];
        #pragma unroll
        for (int nt = 0; nt < 8; nt++)
            #pragma unroll
            for (int c = 0; c < 4; c++) S[nt][c] = 0.f;
        #pragma unroll
        for (int k0 = 0; k0 < 4; k0++) {
            #pragma unroll
            for (int nt = 0; nt < 8; nt++) {
                uint32_t kh2[2], kl2[2];
                uint32_t kaddr_h = smem_u32(&KS[0][nt*8 + (l16 & 7)][k0*16 + ((l16 >> 3) & 1)*8]);
                uint32_t kaddr_l = smem_u32(&KS[1][nt*8 + (l16 & 7)][k0*16 + ((l16 >> 3) & 1)*8]);
                ldsm2(kh2, kaddr_h);
                ldsm2(kl2, kaddr_l);
                mma_bf16(S[nt], Qa[k0][0], kh2);
                mma_bf16(S[nt], Qa[k0][1], kh2);
                mma_bf16(S[nt], Qa[k0][0], kl2);
            }
        }
        #pragma unroll
        for (int nt = 0; nt < 8; nt++) {
            #pragma unroll
            for (int c = 0; c < 4; c++) {
                float v = S[nt][c] * 0.125f;
                if (nb == mb) {
                    int col = nb*64 + nt*8 + tg*2 + (c & 1);
                    int row = (c >= 2) ? myrow1 : myrow0;
                    if (col > row) v = -1e30f;
                }
                S[nt][c] = v;
            }
        }

        float mx0 = -1e30f, mx1 = -1e30f;
        #pragma unroll
        for (int nt = 0; nt < 8; nt++) {
            mx0 = fmaxf(mx0, fmaxf(S[nt][0], S[nt][1]));
            mx1 = fmaxf(mx1, fmaxf(S[nt][2], S[nt][3]));
        }
        mx0 = fmaxf(mx0, __shfl_xor_sync(0xffffffffu, mx0, 1));
        mx0 = fmaxf(mx0, __shfl_xor_sync(0xffffffffu, mx0, 2));
        mx1 = fmaxf(mx1, __shfl_xor_sync(0xffffffffu, mx1, 1));
        mx1 = fmaxf(mx1, __shfl_xor_sync(0xffffffffu, mx1, 2));
        float mn0 = fmaxf(mrow[0], mx0), mn1 = fmaxf(mrow[1], mx1);
        float sc0 = __expf(mrow[0] - mn0), sc1 = __expf(mrow[1] - mn1);
        float sum0 = 0.f, sum1 = 0.f;
        #pragma unroll
        for (int nt = 0; nt < 8; nt++) {
            S[nt][0] = __expf(S[nt][0] - mn0);
            S[nt][1] = __expf(S[nt][1] - mn0);
            S[nt][2] = __expf(S[nt][2] - mn1);
            S[nt][3] = __expf(S[nt][3] - mn1);
            sum0 += S[nt][0] + S[nt][1];
            sum1 += S[nt][2] + S[nt][3];
        }
        sum0 += __shfl_xor_sync(0xffffffffu, sum0, 1);
        sum0 += __shfl_xor_sync(0xffffffffu, sum0, 2);
        sum1 += __shfl_xor_sync(0xffffffffu, sum1, 1);
        sum1 += __shfl_xor_sync(0xffffffffu, sum1, 2);
        lrow[0] = lrow[0]*sc0 + sum0;
        lrow[1] = lrow[1]*sc1 + sum1;
        mrow[0] = mn0; mrow[1] = mn1;
        #pragma unroll
        for (int dt = 0; dt < 8; dt++) {
            O[dt][0] *= sc0; O[dt][1] *= sc0;
            O[dt][2] *= sc1; O[dt][3] *= sc1;
        }

        #pragma unroll
        for (int k0p = 0; k0p < 4; k0p++) {
            const int n0t = 2*k0p, n1t = 2*k0p + 1;
            uint32_t pah[4], pal[4];
            split2u(S[n0t][0], S[n0t][1], pah[0], pal[0]);
            split2u(S[n0t][2], S[n0t][3], pah[1], pal[1]);
            split2u(S[n1t][0], S[n1t][1], pah[2], pal[2]);
            split2u(S[n1t][2], S[n1t][3], pah[3], pal[3]);
            #pragma unroll
            for (int dt = 0; dt < 8; dt++) {
                uint32_t vh2[2], vl2[2];
                ldsm2t(vh2, smem_u32(&VS[0][k0p*16 + l16][dt*8]));
                ldsm2t(vl2, smem_u32(&VS[1][k0p*16 + l16][dt*8]));
                mma_bf16(O[dt], pah, vh2);
                mma_bf16(O[dt], pal, vh2);
                mma_bf16(O[dt], pah, vl2);
            }
        }
        __syncthreads();
    }

    float inv0 = 1.f / lrow[0], inv1 = 1.f / lrow[1];
    #pragma unroll
    for (int dt = 0; dt < 8; dt++) {
        #pragma unroll
        for (int c = 0; c < 4; c++) {
            int row = (c >= 2) ? myrow1 : myrow0;
            int col = h*DH + dt*8 + tg*2 + (c & 1);
            float v = O[dt][c] * ((c >= 2) ? inv1 : inv0);
            __half hh, ll; splith(v, hh, ll);
            size_t off = ((size_t)(b*SEQ + row)) * D_MODEL + col;
            Oh[off] = hh; Ol[off] = ll;
        }
    }
}

// ----------------------------------------------------------------------------
// Legacy SIMT SGEMM (tiny-N heads: N=2, N=4)
// ----------------------------------------------------------------------------
template<bool ACC, bool BIAS>
__global__ void gemm_kernel(const float* __restrict__ A, const float* __restrict__ B,
                            const float* __restrict__ bias, float* __restrict__ C,
                            int M, int N, int K)
{
    __shared__ float As[16][65];
    __shared__ float Bs[16][64];
    const int tid = threadIdx.x;
    const int tx = tid & 15, ty = tid >> 4;
    const int m0 = blockIdx.y * 64, n0 = blockIdx.x * 64;
    const int arow = tid >> 2, akk = (tid & 3) * 4;
    const int bkk = ty, bcol = tx * 4;

    float acc[4][4];
    #pragma unroll
    for (int i = 0; i < 4; i++)
        #pragma unroll
        for (int j = 0; j < 4; j++) acc[i][j] = 0.f;

    for (int k0 = 0; k0 < K; k0 += 16) {
        float4 av = *(const float4*)(A + (size_t)(m0 + arow) * K + k0 + akk);
        As[akk+0][arow] = av.x; As[akk+1][arow] = av.y;
        As[akk+2][arow] = av.z; As[akk+3][arow] = av.w;
        {
            int gn = n0 + bcol;
            const float* Bp = B + (size_t)(k0 + bkk) * N + gn;
            float4 bv;
            if (gn + 3 < N) bv = *(const float4*)Bp;
            else {
                bv.x = (gn+0 < N) ? Bp[0] : 0.f;
                bv.y = (gn+1 < N) ? Bp[1] : 0.f;
                bv.z = (gn+2 < N) ? Bp[2] : 0.f;
                bv.w = (gn+3 < N) ? Bp[3] : 0.f;
            }
            *(float4*)&Bs[bkk][bcol] = bv;
        }
        __syncthreads();
        #pragma unroll
        for (int kk = 0; kk < 16; kk++) {
            float a0 = As[kk][ty*4+0], a1 = As[kk][ty*4+1];
            float a2 = As[kk][ty*4+2], a3 = As[kk][ty*4+3];
            float4 bv = *(const float4*)&Bs[kk][tx*4];
            acc[0][0] += a0*bv.x; acc[0][1] += a0*bv.y; acc[0][2] += a0*bv.z; acc[0][3] += a0*bv.w;
            acc[1][0] += a1*bv.x; acc[1][1] += a1*bv.y; acc[1][2] += a1*bv.z; acc[1][3] += a1*bv.w;
            acc[2][0] += a2*bv.x; acc[2][1] += a2*bv.y; acc[2][2] += a2*bv.z; acc[2][3] += a2*bv.w;
            acc[3][0] += a3*bv.x; acc[3][1] += a3*bv.y; acc[3][2] += a3*bv.z; acc[3][3] += a3*bv.w;
        }
        __syncthreads();
    }
    #pragma unroll
    for (int i = 0; i < 4; i++) {
        int gm = m0 + ty*4 + i;
        #pragma unroll
        for (int j = 0; j < 4; j++) {
            int gn = n0 + tx*4 + j;
            if (gn < N) {
                float v = acc[i][j];
                if (BIAS) v += bias[gn];
                size_t off = (size_t)gm * N + gn;
                if (ACC) v += C[off];
                C[off] = v;
            }
        }
    }
}

// ----------------------------------------------------------------------------
// box Fourier features -> fp16 hi/lo planes
// ----------------------------------------------------------------------------
__global__ void boxsin_kernel(const float* __restrict__ box,
                              __half* __restrict__ h, __half* __restrict__ l)
{
    int idx = blockIdx.x * blockDim.x + threadIdx.x;     // ROWS*4*96
    if (idx >= ROWS*4*96) return;
    int j   = idx % 96;
    int i   = (idx / 96) & 3;
    int row = idx / 384;
    float theta = expf(-(float)j * (LN1E4 / 96.f));
    float ang = box[row*4 + i] * theta;
    float s, c;
    sincosf(ang, &s, &c);
    size_t off = (size_t)row*D_MODEL + i*192 + 2*j;
    __half hh, ll;
    splith(c, hh, ll); h[off] = hh;   l[off] = ll;
    splith(s, hh, ll); h[off+1] = hh; l[off+1] = ll;
}

// ----------------------------------------------------------------------------
// RMSNorm -> optional f32 out + fp16 hi (+ optional lo) planes
// ----------------------------------------------------------------------------
__global__ void rmsnorm_kernel(const float* __restrict__ x, const float* __restrict__ w,
                               float* __restrict__ out,
                               __half* __restrict__ oh, __half* __restrict__ ol)
{
    __shared__ float red[256];
    int row = blockIdx.x;
    const float* xr = x + (size_t)row * D_MODEL;
    float s = 0.f;
    for (int i = threadIdx.x; i < D_MODEL; i += 256) { float v = xr[i]; s += v*v; }
    red[threadIdx.x] = s; __syncthreads();
    for (int off = 128; off > 0; off >>= 1) {
        if (threadIdx.x < off) red[threadIdx.x] += red[threadIdx.x + off];
        __syncthreads();
    }
    float inv = rsqrtf(red[0] / (float)D_MODEL + 1e-6f);
    for (int i = threadIdx.x; i < D_MODEL; i += 256) {
        float v = xr[i] * inv * w[i];
        if (out) out[(size_t)row * D_MODEL + i] = v;
        if (oh) {
            if (ol) {
                __half hh, ll; splith(v, hh, ll);
                oh[(size_t)row * D_MODEL + i] = hh;
                ol[(size_t)row * D_MODEL + i] = ll;
            } else {
                oh[(size_t)row * D_MODEL + i] = __float2half_rn(v);
            }
        }
    }
}

// ----------------------------------------------------------------------------
// Launch
// ----------------------------------------------------------------------------
extern "C" void kernel_launch(void* const* d_in, const int* in_sizes, int n_in,
                              void* d_out, int out_size)
{
    const float* patch        = (const float*)d_in[0];
    const float* box          = (const float*)d_in[1];
    const float* patch_W      = (const float*)d_in[2];
    const float* patch_b      = (const float*)d_in[3];
    const float* box_W        = (const float*)d_in[4];
    const float* box_b        = (const float*)d_in[5];
    const float* Wq           = (const float*)d_in[6];
    const float* Wk           = (const float*)d_in[7];
    const float* Wv           = (const float*)d_in[8];
    const float* Wo           = (const float*)d_in[9];
    const float* attn_norm_w  = (const float*)d_in[10];
    const float* gate_W       = (const float*)d_in[11];
    const float* hidden_W     = (const float*)d_in[12];
    const float* ffn_out_W    = (const float*)d_in[13];
    const float* ffn_norm_w   = (const float*)d_in[14];
    const float* reward_norm_w= (const float*)d_in[15];
    const float* reward_W     = (const float*)d_in[16];
    const float* reward_b     = (const float*)d_in[17];
    const float* label_norm_w = (const float*)d_in[18];
    const float* label_W      = (const float*)d_in[19];
    const float* label_b      = (const float*)d_in[20];
    const float* box_norm_w   = (const float*)d_in[21];
    const float* boxh_W       = (const float*)d_in[22];
    const float* boxh_b       = (const float*)d_in[23];
    float* out = (float*)d_out;

    float *x, *hn, *qkv;
    float2* rope;
    __half *pw,*bw,*qkvW,*woW,*ghW,*owW,*lw;
    __half *pah,*pal,*bsh,*bsl,*hnh,*hnl,*oah,*oal,*gsh;
    { void* p;
      cudaGetSymbolAddress(&p, g_x);    x    = (float*)p;
      cudaGetSymbolAddress(&p, g_hn);   hn   = (float*)p;
      cudaGetSymbolAddress(&p, g_qkv);  qkv  = (float*)p;
      cudaGetSymbolAddress(&p, g_rope); rope = (float2*)p;
      cudaGetSymbolAddress(&p, g_pw);   pw   = (__half*)p;
      cudaGetSymbolAddress(&p, g_bw);   bw   = (__half*)p;
      cudaGetSymbolAddress(&p, g_qkvW); qkvW = (__half*)p;
      cudaGetSymbolAddress(&p, g_woW);  woW  = (__half*)p;
      cudaGetSymbolAddress(&p, g_ghW);  ghW  = (__half*)p;
      cudaGetSymbolAddress(&p, g_owW);  owW  = (__half*)p;
      cudaGetSymbolAddress(&p, g_lw);   lw   = (__half*)p;
      cudaGetSymbolAddress(&p, g_pah);  pah  = (__half*)p;
      cudaGetSymbolAddress(&p, g_pal);  pal  = (__half*)p;
      cudaGetSymbolAddress(&p, g_bsh);  bsh  = (__half*)p;
      cudaGetSymbolAddress(&p, g_bsl);  bsl  = (__half*)p;
      cudaGetSymbolAddress(&p, g_hnh);  hnh  = (__half*)p;
      cudaGetSymbolAddress(&p, g_hnl);  hnl  = (__half*)p;
      cudaGetSymbolAddress(&p, g_oah);  oah  = (__half*)p;
      cudaGetSymbolAddress(&p, g_oal);  oal  = (__half*)p;
      cudaGetSymbolAddress(&p, g_gsh);  gsh  = (__half*)p;
    }

    const dim3 m768 (D_MODEL/128, ROWS/128);
    const dim3 m2304(3*D_MODEL/128, ROWS/128);
    const dim3 m6144(2*DFF/128, ROWS/128);
    const dim3 m1024(1024/128, ROWS/128);

    // ---- conversions ----
    rope_table_kernel<<<(SEQ*32 + 255)/256, 256>>>(rope);
    {
        int n = ROWS * 4 * 96;
        boxsin_kernel<<<(n + 255) / 256, 256>>>(box, bsh, bsl);
    }
    cvt_split_kernel<<<1024, 256>>>(patch, pah, pal, (size_t)ROWS*D_MODEL);
    cvt_w_kernel<<<1024, 256>>>(patch_W, pw, (size_t)D_MODEL*D_MODEL);
    cvt_w_kernel<<<1024, 256>>>(box_W,   bw, (size_t)D_MODEL*D_MODEL);
    // ---- Embedding ----
    fp16_gemm_kernel<false, true, false, true><<<m768, 256>>>(pah, pal, pw, patch_b, x, nullptr, nullptr, ROWS, D_MODEL, D_MODEL, D_MODEL);
    fp16_gemm_kernel<true,  true, false, true><<<m768, 256>>>(bsh, bsl, bw, box_b,   x, nullptr, nullptr, ROWS, D_MODEL, D_MODEL, D_MODEL);
    // remaining weight conversions
    cvt_qkv_kernel<<<4096, 256>>>(Wq, Wk, Wv, qkvW);
    cvt_w_kernel<<<2048, 256>>>(Wo, woW, (size_t)WQKVO);
    cvt_gh_kernel<<<4096, 256>>>(gate_W, hidden_W, ghW);
    cvt_w_kernel<<<2048, 256>>>(ffn_out_W, owW, (size_t)WFF);
    cvt_label_kernel<<<(D_MODEL*1024 + 255)/256, 256>>>(label_W, lw);

    // ---- Layers ----
    for (int L = 0; L < NLAYERS; L++) {
        const size_t qoff = (size_t)L * D_MODEL * 3*D_MODEL;
        const size_t woff = (size_t)L * D_MODEL * D_MODEL;
        const size_t goff = (size_t)L * D_MODEL * 2*DFF;
        const size_t foff = (size_t)L * D_MODEL * DFF;
        const float* anw = attn_norm_w + (size_t)L * D_MODEL;
        const float* fnw = ffn_norm_w + (size_t)L * D_MODEL;

        // attention (2-term: error < TF32)
        rmsnorm_kernel<<<ROWS, 256>>>(x, anw, (float*)nullptr, hnh, hnl);
        fp16_gemm_kernel<false, false, false, true><<<m2304, 256>>>(hnh, hnl, qkvW + qoff, nullptr, qkv, nullptr, nullptr, ROWS, 3*D_MODEL, 3*D_MODEL, D_MODEL);
        flash_kernel<<<dim3(SEQ/64, BATCH*NH), 128>>>(qkv, rope, oah, oal);
        fp16_gemm_kernel<true, false, false, true><<<m768, 256>>>(oah, oal, woW + woff, nullptr, x, nullptr, nullptr, ROWS, D_MODEL, D_MODEL, D_MODEL);

        // FFN (single-term: TF32-equivalent error, validated passing at 8.96e-4)
        rmsnorm_kernel<<<ROWS, 256>>>(x, fnw, (float*)nullptr, hnh, (__half*)nullptr);
        fp16_gemm_kernel<false, false, true, false><<<m6144, 256>>>(hnh, nullptr, ghW + goff, nullptr, nullptr, gsh, nullptr, ROWS, 2*DFF, 2*DFF, D_MODEL);
        fp16_gemm_kernel<true, false, false, false><<<m768, 256>>>(gsh, nullptr, owW + foff, nullptr, x, nullptr, nullptr, ROWS, D_MODEL, D_MODEL, DFF);
    }

    // ---- Heads ----
    float* out_reward = out;
    float* out_label  = out + (size_t)ROWS * 2;
    float* out_box    = out + (size_t)ROWS * 2 + (size_t)ROWS * 1000;

    rmsnorm_kernel<<<ROWS, 256>>>(x, reward_norm_w, hn, (__half*)nullptr, (__half*)nullptr);
    gemm_kernel<false, true><<<dim3(1, ROWS/64), 256>>>(hn, reward_W, reward_b, out_reward, ROWS, 2, D_MODEL);

    rmsnorm_kernel<<<ROWS, 256>>>(x, label_norm_w, (float*)nullptr, hnh, hnl);
    fp16_gemm_kernel<false, true, false, true><<<m1024, 256>>>(hnh, hnl, lw, label_b, out_label, nullptr, nullptr, ROWS, 1000, 1024, D_MODEL);

    rmsnorm_kernel<<<ROWS, 256>>>(x, box_norm_w, hn, (__half*)nullptr, (__half*)nullptr);
    gemm_kernel<false, true><<<dim3(1, ROWS/64), 256>>>(hn, boxh_W, boxh_b, out_box, ROWS, 4, D_MODEL);
}